// round 14
// baseline (speedup 1.0000x reference)
#include <cuda_runtime.h>
#include <cuda_bf16.h>
#include <math.h>
#include <stdint.h>

#define B_   32
#define N_   196
#define E_   512
#define H_   8
#define HD_  64
#define L_   4
#define M_   (B_*N_)          // 6272 tokens
#define PD_  3840             // patch dim
#define NCLS_ 101
#define EPS_ 1e-5f

// ---------------- scratch (device globals; no cudaMalloc allowed) ------------
__device__ float g_x[2*M_*E_];
__device__ float g_qkv[(size_t)2*M_*3*E_];
__device__ float g_q[M_*E_];
__device__ float g_kv[M_*2*E_];
__device__ float g_sc[(size_t)2*B_*H_*N_*N_];
__device__ float g_feat[B_*2*E_];
__device__ float g_clsh[B_*4*E_];
// bf16 hi/lo split buffers (words = elems/2)
#define MAXA_W 12845056   // (12544*2048)/2
#define MAXW_W 983040     // (512*3840)/2  (largest weight: patch_w)
__device__ uint32_t g_bfAhi[MAXA_W];
__device__ uint32_t g_bfAlo[MAXA_W];
__device__ uint32_t g_bfA2hi[MAXA_W];
__device__ uint32_t g_bfA2lo[MAXA_W];
__device__ uint32_t g_bfWhi[MAXW_W];
__device__ uint32_t g_bfWlo[MAXW_W];

// ---------------- PTX helpers (base compute_100-safe) ------------------------
__device__ __forceinline__ uint32_t smem_u32(const void* p) {
    uint32_t a;
    asm("{ .reg .u64 t; cvta.to.shared.u64 t, %1; cvt.u32.u64 %0, t; }" : "=r"(a) : "l"(p));
    return a;
}
__device__ __forceinline__ void ldm_x4(uint32_t addr, uint32_t* r) {
    asm volatile("ldmatrix.sync.aligned.m8n8.x4.shared.b16 {%0,%1,%2,%3}, [%4];"
        : "=r"(r[0]), "=r"(r[1]), "=r"(r[2]), "=r"(r[3]) : "r"(addr));
}
__device__ __forceinline__ void mma16816(float* c, const uint32_t* a, const uint32_t* b) {
    asm volatile("mma.sync.aligned.m16n8k16.row.col.f32.bf16.bf16.f32 "
        "{%0,%1,%2,%3}, {%4,%5,%6,%7}, {%8,%9}, {%0,%1,%2,%3};"
        : "+f"(c[0]), "+f"(c[1]), "+f"(c[2]), "+f"(c[3])
        : "r"(a[0]), "r"(a[1]), "r"(a[2]), "r"(a[3]), "r"(b[0]), "r"(b[1]));
}
__device__ __forceinline__ void cp16(uint32_t dst, const void* src) {
    asm volatile("cp.async.ca.shared.global [%0], [%1], 16;" :: "r"(dst), "l"(src));
}
#define CP_COMMIT() asm volatile("cp.async.commit_group;" ::: "memory")

__device__ __forceinline__ uint32_t pack_bf(float a, float b) {
    __nv_bfloat16 x = __float2bfloat16(a), y = __float2bfloat16(b);
    return ((uint32_t)__bfloat16_as_ushort(y) << 16) | __bfloat16_as_ushort(x);
}
__device__ __forceinline__ void split2(float a, float b, uint32_t& hi, uint32_t& lo) {
    __nv_bfloat16 ha = __float2bfloat16(a), hb = __float2bfloat16(b);
    hi = ((uint32_t)__bfloat16_as_ushort(hb) << 16) | __bfloat16_as_ushort(ha);
    lo = pack_bf(a - __bfloat162float(ha), b - __bfloat162float(hb));
}
__device__ __forceinline__ void cvt_hilo(float4 v, uint32_t& hi0, uint32_t& hi1,
                                         uint32_t& lo0, uint32_t& lo1) {
    split2(v.x, v.y, hi0, lo0);
    split2(v.z, v.w, hi1, lo1);
}

// ---------------- split: fp32 -> bf16 hi + lo --------------------------------
__global__ void split_kernel(const float4* __restrict__ in,
                             uint2* __restrict__ hi, uint2* __restrict__ lo, long n4)
{
    long i = (long)blockIdx.x * blockDim.x + threadIdx.x;
    if (i >= n4) return;
    float4 v = in[i];
    uint32_t h0, h1, l0, l1;
    cvt_hilo(v, h0, h1, l0, l1);
    hi[i] = make_uint2(h0, h1);
    lo[i] = make_uint2(l0, l1);
}

// ======= bf16 tensor-core GEMM: CTA 128x128, warp 64x32, 2-stage, occ 2 ======
// C = act(A@W^T + bias [+res]); optional bf16 hi/lo split output; both allowed.
// Requires M%128==0, N%128==0, K%32==0.
#define ROWB 80
#define HOFF 10240                 // 128 rows x 80B per operand-half
#define OFF_AL (1*HOFF)
#define OFF_BH (2*HOFF)
#define OFF_BL (3*HOFF)
#define BUFB   (4*HOFF)            // 40960
#define GSMEM  (2*BUFB)            // 81920 -> 2 CTAs/SM

__global__ __launch_bounds__(256, 2)
void gemm_bf16_kernel(const __nv_bfloat16* __restrict__ Ahi,
                      const __nv_bfloat16* __restrict__ Alo,
                      const __nv_bfloat16* __restrict__ Bhi,
                      const __nv_bfloat16* __restrict__ Blo,
                      const float* __restrict__ bias,
                      const float* __restrict__ res,
                      float* __restrict__ C,
                      uint32_t* __restrict__ outHi,
                      uint32_t* __restrict__ outLo,
                      int M, int N, int K, int relu,
                      long sA, long sW, long sB, long sRes, long sC)
{
    int z = blockIdx.z;
    Ahi += (size_t)z * sA;  Alo += (size_t)z * sA;
    Bhi += (size_t)z * sW;  Blo += (size_t)z * sW;
    bias += (size_t)z * sB;
    if (res) res += (size_t)z * sRes;
    if (C)   C   += (size_t)z * sC;
    if (outHi) { outHi += (size_t)z * (sC >> 1); outLo += (size_t)z * (sC >> 1); }

    extern __shared__ char sm[];
    const uint32_t sbase = smem_u32(sm);
    const int tid = threadIdx.x, wid = tid >> 5, lane = tid & 31;
    const int m0 = blockIdx.y * 128, n0 = blockIdx.x * 128;
    const int wm = wid >> 2, wn = wid & 3;       // 2x4 warp grid; warp tile 64x32

    float acc[4][4][4];
#pragma unroll
    for (int i = 0; i < 4; i++)
#pragma unroll
        for (int j = 0; j < 4; j++)
#pragma unroll
            for (int r = 0; r < 4; r++) acc[i][j][r] = 0.f;

    // cp.async: 512 16B-chunks per operand-half; 2 per thread per half
    const int c0row = tid >> 2, c0c = tid & 3;
    const int c1row = (tid + 256) >> 2, c1c = (tid + 256) & 3;

    auto issue = [&](int s, int buf) {
        uint32_t base = sbase + buf * BUFB;
        long kb = (long)s * 32;
        cp16(base + c0row * ROWB + c0c * 16,          Ahi + (size_t)(m0 + c0row) * K + kb + c0c * 8);
        cp16(base + OFF_AL + c0row * ROWB + c0c * 16, Alo + (size_t)(m0 + c0row) * K + kb + c0c * 8);
        cp16(base + c1row * ROWB + c1c * 16,          Ahi + (size_t)(m0 + c1row) * K + kb + c1c * 8);
        cp16(base + OFF_AL + c1row * ROWB + c1c * 16, Alo + (size_t)(m0 + c1row) * K + kb + c1c * 8);
        cp16(base + OFF_BH + c0row * ROWB + c0c * 16, Bhi + (size_t)(n0 + c0row) * K + kb + c0c * 8);
        cp16(base + OFF_BL + c0row * ROWB + c0c * 16, Blo + (size_t)(n0 + c0row) * K + kb + c0c * 8);
        cp16(base + OFF_BH + c1row * ROWB + c1c * 16, Bhi + (size_t)(n0 + c1row) * K + kb + c1c * 8);
        cp16(base + OFF_BL + c1row * ROWB + c1c * 16, Blo + (size_t)(n0 + c1row) * K + kb + c1c * 8);
    };

    const uint32_t aR = (uint32_t)(wm * 64 + (lane & 7) + ((lane >> 3) & 1) * 8);
    const uint32_t aC = (uint32_t)((lane >> 4) * 8);
    const uint32_t bR = (uint32_t)(wn * 32 + (lane & 7) + (lane >> 4) * 8);
    const uint32_t bC = (uint32_t)(((lane >> 3) & 1) * 8);

    auto compute = [&](int buf) {
        uint32_t bb = sbase + buf * BUFB;
#pragma unroll
        for (int kk = 0; kk < 32; kk += 16) {
            uint32_t ah[4][4], al[4][4], bh[2][4], bl[2][4];
#pragma unroll
            for (int mt = 0; mt < 4; mt++) {
                uint32_t off = (aR + mt * 16) * ROWB + (kk + aC) * 2;
                ldm_x4(bb + off, ah[mt]);
                ldm_x4(bb + OFF_AL + off, al[mt]);
            }
#pragma unroll
            for (int nt2 = 0; nt2 < 2; nt2++) {
                uint32_t off = (bR + nt2 * 16) * ROWB + (kk + bC) * 2;
                ldm_x4(bb + OFF_BH + off, bh[nt2]);
                ldm_x4(bb + OFF_BL + off, bl[nt2]);
            }
#pragma unroll
            for (int mt = 0; mt < 4; mt++)
#pragma unroll
                for (int nt = 0; nt < 4; nt++) {
                    const uint32_t* bhp = &bh[nt >> 1][(nt & 1) * 2];
                    const uint32_t* blp = &bl[nt >> 1][(nt & 1) * 2];
                    mma16816(acc[mt][nt], ah[mt], bhp);
                    mma16816(acc[mt][nt], ah[mt], blp);
                    mma16816(acc[mt][nt], al[mt], bhp);
                }
        }
    };

    const int nslab = K >> 5;
    issue(0, 0); CP_COMMIT();
    for (int s = 0; s < nslab; s++) {
        if (s + 1 < nslab) { issue(s + 1, (s + 1) & 1); CP_COMMIT(); }
        if (s + 1 < nslab) asm volatile("cp.async.wait_group 1;" ::: "memory");
        else               asm volatile("cp.async.wait_group 0;" ::: "memory");
        __syncthreads();
        compute(s & 1);
        __syncthreads();
    }

    // epilogue
#pragma unroll
    for (int mt = 0; mt < 4; mt++)
#pragma unroll
        for (int nt = 0; nt < 4; nt++) {
            int m = m0 + wm * 64 + mt * 16 + (lane >> 2);
            int n = n0 + wn * 32 + nt * 8 + (lane & 3) * 2;
            float b0 = bias[n], b1 = bias[n + 1];
#pragma unroll
            for (int half = 0; half < 2; half++) {
                int mm = m + half * 8;
                float v0 = acc[mt][nt][half * 2]     + b0;
                float v1 = acc[mt][nt][half * 2 + 1] + b1;
                if (res) {
                    float2 r2 = *reinterpret_cast<const float2*>(res + (size_t)mm * N + n);
                    v0 += r2.x; v1 += r2.y;
                }
                if (relu) { v0 = fmaxf(v0, 0.f); v1 = fmaxf(v1, 0.f); }
                if (C)
                    *reinterpret_cast<float2*>(C + (size_t)mm * N + n) = make_float2(v0, v1);
                if (outHi) {
                    uint32_t hw, lw;
                    split2(v0, v1, hw, lw);
                    size_t wi = (size_t)mm * (N >> 1) + (n >> 1);
                    outHi[wi] = hw; outLo[wi] = lw;
                }
            }
        }
}

// ------- fallback SIMT GEMM (head; any shape) --------------------------------
#define BM 128
#define BN 64
#define BK 16
__global__ __launch_bounds__(256, 2)
void gemm_kernel(const float* __restrict__ A,
                 const float* __restrict__ W,
                 const float* __restrict__ bias,
                 const float* __restrict__ res,
                 float* __restrict__ C,
                 int M, int N, int K, int relu)
{
    __shared__ float As[BK][BM+4];
    __shared__ float Ws[BK][BN+4];
    int tid = threadIdx.x;
    int tx = tid & 15, ty = tid >> 4;
    int m0 = blockIdx.y * BM, n0 = blockIdx.x * BN;
    float acc[8][4];
#pragma unroll
    for (int i = 0; i < 8; i++)
#pragma unroll
        for (int j = 0; j < 4; j++) acc[i][j] = 0.f;

    for (int k0 = 0; k0 < K; k0 += BK) {
#pragma unroll
        for (int t = 0; t < 2; t++) {
            int f = tid + t * 256;
            int r = f >> 2, kq = (f & 3) << 2;
            int m = m0 + r;
            float4 v = make_float4(0.f,0.f,0.f,0.f);
            if (m < M) v = *reinterpret_cast<const float4*>(A + (size_t)m*K + k0 + kq);
            As[kq][r]   = v.x; As[kq+1][r] = v.y;
            As[kq+2][r] = v.z; As[kq+3][r] = v.w;
        }
        {
            int r = tid >> 2, kq = (tid & 3) << 2;
            int n = n0 + r;
            float4 v = make_float4(0.f,0.f,0.f,0.f);
            if (n < N) v = *reinterpret_cast<const float4*>(W + (size_t)n*K + k0 + kq);
            Ws[kq][r]   = v.x; Ws[kq+1][r] = v.y;
            Ws[kq+2][r] = v.z; Ws[kq+3][r] = v.w;
        }
        __syncthreads();
#pragma unroll
        for (int kk = 0; kk < BK; kk++) {
            float a[8], b[4];
            *reinterpret_cast<float4*>(a)   = *reinterpret_cast<const float4*>(&As[kk][ty*8]);
            *reinterpret_cast<float4*>(a+4) = *reinterpret_cast<const float4*>(&As[kk][ty*8+4]);
            *reinterpret_cast<float4*>(b)   = *reinterpret_cast<const float4*>(&Ws[kk][tx*4]);
#pragma unroll
            for (int i = 0; i < 8; i++)
#pragma unroll
                for (int j = 0; j < 4; j++)
                    acc[i][j] += a[i]*b[j];
        }
        __syncthreads();
    }
#pragma unroll
    for (int i = 0; i < 8; i++) {
        int m = m0 + ty*8 + i;
        if (m >= M) continue;
#pragma unroll
        for (int j = 0; j < 4; j++) {
            int n = n0 + tx*4 + j;
            if (n >= N) continue;
            float v = acc[i][j] + bias[n];
            if (res) v += res[(size_t)m*N + n];
            if (relu) v = fmaxf(v, 0.f);
            C[(size_t)m*N + n] = v;
        }
    }
}

// ---------------- LayerNorm over 512 -> bf16 hi/lo split ---------------------
__global__ void ln_split_kernel(const float* __restrict__ x,
                                const float* __restrict__ g,
                                const float* __restrict__ b,
                                uint32_t* __restrict__ hi,
                                uint32_t* __restrict__ lo)
{
    int row = blockIdx.x;
    const float* xr = x + (size_t)row * E_;
    int tid = threadIdx.x;
    float2 v = *reinterpret_cast<const float2*>(xr + 2*tid);
    float s  = v.x + v.y;
    float ss = v.x*v.x + v.y*v.y;
#pragma unroll
    for (int o = 16; o > 0; o >>= 1) {
        s  += __shfl_xor_sync(0xffffffffu, s,  o);
        ss += __shfl_xor_sync(0xffffffffu, ss, o);
    }
    __shared__ float sh[16];
    int w = tid >> 5, lane = tid & 31;
    if (lane == 0) { sh[w] = s; sh[8+w] = ss; }
    __syncthreads();
    if (tid == 0) {
        float a = 0.f, c = 0.f;
        for (int i = 0; i < 8; i++) { a += sh[i]; c += sh[8+i]; }
        sh[0] = a; sh[8] = c;
    }
    __syncthreads();
    float mean = sh[0] * (1.f/E_);
    float var  = sh[8] * (1.f/E_) - mean*mean;
    float rs = rsqrtf(var + EPS_);
    float2 gg = *reinterpret_cast<const float2*>(g + 2*tid);
    float2 bb = *reinterpret_cast<const float2*>(b + 2*tid);
    float y0 = (v.x - mean) * rs * gg.x + bb.x;
    float y1 = (v.y - mean) * rs * gg.y + bb.y;
    uint32_t hw, lw;
    split2(y0, y1, hw, lw);
    size_t wi = (size_t)row * 256 + tid;
    hi[wi] = hw; lo[wi] = lw;
}

// ------- shifted-patch gather + LN(3840) -> bf16 hi/lo split -----------------
__global__ void patch_ln_kernel(const float* __restrict__ image,
                                const float* __restrict__ g,
                                const float* __restrict__ bb,
                                uint32_t* __restrict__ hi,
                                uint32_t* __restrict__ lo)
{
    __shared__ float buf[PD_];
    __shared__ float sh[16];
    int bn = blockIdx.x;
    int b  = bn / N_, n = bn % N_;
    int ph = n / 14, pw = n % 14;
    int tid = threadIdx.x;

    float s = 0.f, ss = 0.f;
    for (int d = tid; d < PD_; d += 256) {
        int c  = d % 15, t = d / 15;
        int p2 = t % 16, p1 = t / 16;
        int sh_idx = c / 3, ch = c % 3;
        int row = ph*16 + p1, col = pw*16 + p2;
        if      (sh_idx == 1) col -= 1;
        else if (sh_idx == 2) col += 1;
        else if (sh_idx == 3) row -= 1;
        else if (sh_idx == 4) row += 1;
        float v = 0.f;
        if (row >= 0 && row < 224 && col >= 0 && col < 224)
            v = image[(((size_t)b*3 + ch)*224 + row)*224 + col];
        buf[d] = v;
        s += v; ss += v*v;
    }
#pragma unroll
    for (int o = 16; o > 0; o >>= 1) {
        s  += __shfl_xor_sync(0xffffffffu, s,  o);
        ss += __shfl_xor_sync(0xffffffffu, ss, o);
    }
    int w = tid >> 5, lane = tid & 31;
    if (lane == 0) { sh[w] = s; sh[8+w] = ss; }
    __syncthreads();
    if (tid == 0) {
        float a = 0.f, c = 0.f;
        for (int i = 0; i < 8; i++) { a += sh[i]; c += sh[8+i]; }
        sh[0] = a; sh[8] = c;
    }
    __syncthreads();
    float mean = sh[0] * (1.f/PD_);
    float var  = sh[8] * (1.f/PD_) - mean*mean;
    float rs = rsqrtf(var + EPS_);
    uint32_t* hrow = hi + (size_t)bn * (PD_/2);
    uint32_t* lrow = lo + (size_t)bn * (PD_/2);
    for (int d = 2*tid; d < PD_; d += 512) {
        float y0 = (buf[d]   - mean) * rs * g[d]   + bb[d];
        float y1 = (buf[d+1] - mean) * rs * g[d+1] + bb[d+1];
        uint32_t hw, lw;
        split2(y0, y1, hw, lw);
        hrow[d >> 1] = hw; lrow[d >> 1] = lw;
    }
}

// ---------------- positional add (buggy batch-indexed sinusoid, per ref) -----
__global__ void posadd_kernel()
{
    int idx = blockIdx.x * 256 + threadIdx.x;
    if (idx >= 2*M_*E_) return;
    int e = idx & (E_-1);
    int stream_rem = idx % (M_*E_);
    int b = stream_rem / (N_*E_);
    float p = (float)(b + 1);
    int i = e & 255;
    float f = expf(-(float)i * (9.210340371976184f / 255.0f));
    float ang = p * f;
    float v = (e < 256) ? sinf(ang) : cosf(ang);
    g_x[idx] += v;
}

// ---------------- attention: scores = scale * Q K^T  (batched over z) --------
__global__ void scores_kernel(const float* __restrict__ Qp,
                              const float* __restrict__ Kp,
                              int qstride, int kstride,
                              long qz, long kz, float scale)
{
    int zz = blockIdx.z;
    int z  = zz >> 8;
    int bh = zz & 255;
    int b = bh >> 3, h = bh & 7;
    Qp += (size_t)z * qz;
    Kp += (size_t)z * kz;
    float* sc = g_sc + (size_t)zz * N_ * N_;
    int q0 = blockIdx.y * 16, k0 = blockIdx.x * 16;
    __shared__ float qs[16][68];
    __shared__ float ks[16][68];
    int tid = threadIdx.x;
    int r = tid >> 4, c4 = (tid & 15) * 4;
    {
        int q = q0 + r;
        float4 v = make_float4(0.f,0.f,0.f,0.f);
        if (q < N_) v = *reinterpret_cast<const float4*>(Qp + (size_t)(b*N_+q)*qstride + h*HD_ + c4);
        qs[r][c4]=v.x; qs[r][c4+1]=v.y; qs[r][c4+2]=v.z; qs[r][c4+3]=v.w;
        int k = k0 + r;
        float4 w = make_float4(0.f,0.f,0.f,0.f);
        if (k < N_) w = *reinterpret_cast<const float4*>(Kp + (size_t)(b*N_+k)*kstride + h*HD_ + c4);
        ks[r][c4]=w.x; ks[r][c4+1]=w.y; ks[r][c4+2]=w.z; ks[r][c4+3]=w.w;
    }
    __syncthreads();
    int ty = tid >> 4, tx = tid & 15;
    float s = 0.f;
#pragma unroll
    for (int d = 0; d < HD_; d++) s += qs[ty][d] * ks[tx][d];
    int q = q0 + ty, k = k0 + tx;
    if (q < N_ && k < N_)
        sc[(size_t)q*N_ + k] = s * scale;
}

// ---------------- row softmax over 196 ---------------------------------------
__global__ void softmax_kernel(int nrows)
{
    int gw = (blockIdx.x * blockDim.x + threadIdx.x) >> 5;
    if (gw >= nrows) return;
    int lane = threadIdx.x & 31;
    float* row = g_sc + (size_t)gw * N_;
    float vals[7];
    float mx = -1e30f;
#pragma unroll
    for (int i = 0; i < 7; i++) {
        int j = lane + 32*i;
        vals[i] = (j < N_) ? row[j] : -1e30f;
        mx = fmaxf(mx, vals[i]);
    }
#pragma unroll
    for (int o = 16; o > 0; o >>= 1) mx = fmaxf(mx, __shfl_xor_sync(0xffffffffu, mx, o));
    float sum = 0.f;
#pragma unroll
    for (int i = 0; i < 7; i++) { vals[i] = expf(vals[i] - mx); sum += vals[i]; }
#pragma unroll
    for (int o = 16; o > 0; o >>= 1) sum += __shfl_xor_sync(0xffffffffu, sum, o);
    float inv = 1.f / sum;
#pragma unroll
    for (int i = 0; i < 7; i++) {
        int j = lane + 32*i;
        if (j < N_) row[j] = vals[i] * inv;
    }
}

// ------- PV (batched over z), writes bf16 hi/lo split directly ---------------
__global__ void pv_kernel(const float* __restrict__ Vp, int vstride,
                          long vz, long ozw,
                          uint32_t* __restrict__ outHi,
                          uint32_t* __restrict__ outLo)
{
    int zz = blockIdx.y;
    int z  = zz >> 8;
    int bh = zz & 255;
    int b = bh >> 3, h = bh & 7;
    Vp    += (size_t)z * vz;
    outHi += (size_t)z * ozw;
    outLo += (size_t)z * ozw;
    const float* P = g_sc + (size_t)zz * N_ * N_;
    int q0 = blockIdx.x * 32;
    __shared__ float Ps[32][17];
    __shared__ float Vs[16][64];
    int tid = threadIdx.x;
    int l32 = tid & 31, ty = tid >> 5;        // 8 q-rows per pass; 2 cols per thread
    int tx2 = l32 * 2;
    float acc[4][2];
#pragma unroll
    for (int i = 0; i < 4; i++) { acc[i][0] = 0.f; acc[i][1] = 0.f; }

    for (int k0 = 0; k0 < N_; k0 += 16) {
        {
            int pr = tid >> 3, pc = (tid & 7) * 2;
#pragma unroll
            for (int j = 0; j < 2; j++) {
                int q = q0 + pr, k = k0 + pc + j;
                Ps[pr][pc+j] = (q < N_ && k < N_) ? P[(size_t)q*N_ + k] : 0.f;
            }
        }
        {
            int vr = tid >> 4, vc = (tid & 15) * 4;
            int k = k0 + vr;
            float4 v = make_float4(0.f,0.f,0.f,0.f);
            if (k < N_) v = *reinterpret_cast<const float4*>(Vp + (size_t)(b*N_+k)*vstride + h*HD_ + vc);
            Vs[vr][vc]=v.x; Vs[vr][vc+1]=v.y; Vs[vr][vc+2]=v.z; Vs[vr][vc+3]=v.w;
        }
        __syncthreads();
#pragma unroll
        for (int kk = 0; kk < 16; kk++) {
            float2 vv = *reinterpret_cast<const float2*>(&Vs[kk][tx2]);
#pragma unroll
            for (int i = 0; i < 4; i++) {
                float p = Ps[ty + 8*i][kk];
                acc[i][0] += p * vv.x;
                acc[i][1] += p * vv.y;
            }
        }
        __syncthreads();
    }
#pragma unroll
    for (int i = 0; i < 4; i++) {
        int q = q0 + ty + 8*i;
        if (q < N_) {
            uint32_t hw, lw;
            split2(acc[i][0], acc[i][1], hw, lw);
            size_t wi = (size_t)(b*N_ + q) * (E_/2) + h*(HD_/2) + l32;
            outHi[wi] = hw; outLo[wi] = lw;
        }
    }
}

// ---------------- final LN of last token -> feat (B, 2E) ---------------------
__global__ void final_feat_kernel(const float* __restrict__ g,
                                  const float* __restrict__ b)
{
    int s = blockIdx.x >> 5;
    int bb = blockIdx.x & 31;
    const float* src = g_x + ((size_t)s*M_ + bb*N_ + (N_-1)) * E_;
    int tid = threadIdx.x;
    float v0 = src[tid], v1 = src[tid + 256];
    float ssum = v0 + v1, sq = v0*v0 + v1*v1;
#pragma unroll
    for (int o = 16; o > 0; o >>= 1) {
        ssum += __shfl_xor_sync(0xffffffffu, ssum, o);
        sq   += __shfl_xor_sync(0xffffffffu, sq,   o);
    }
    __shared__ float sh[16];
    int w = tid >> 5, lane = tid & 31;
    if (lane == 0) { sh[w] = ssum; sh[8+w] = sq; }
    __syncthreads();
    if (tid == 0) {
        float a = 0.f, c = 0.f;
        for (int i = 0; i < 8; i++) { a += sh[i]; c += sh[8+i]; }
        sh[0] = a; sh[8] = c;
    }
    __syncthreads();
    float mean = sh[0] * (1.f/E_);
    float var  = sh[8] * (1.f/E_) - mean*mean;
    float rs = rsqrtf(var + EPS_);
    float* dst = g_feat + (size_t)bb * (2*E_) + s*E_;
    dst[tid]       = (v0 - mean) * rs * g[tid]       + b[tid];
    dst[tid + 256] = (v1 - mean) * rs * g[tid + 256] + b[tid + 256];
}

// ---------------- host-side orchestration ------------------------------------
static uint32_t *h_Ahi, *h_Alo, *h_A2hi, *h_A2lo, *h_Whi, *h_Wlo;

static inline void splitTo(const float* src, uint32_t* hi, uint32_t* lo, size_t n)
{
    long n4 = (long)(n >> 2);
    split_kernel<<<(unsigned)((n4 + 255) / 256), 256>>>(
        (const float4*)src, (uint2*)hi, (uint2*)lo, n4);
}
static inline void gemmT(const uint32_t* aHi, const uint32_t* aLo, long wElemOff,
                         const float* bias, const float* res, float* C,
                         uint32_t* oHi, uint32_t* oLo,
                         int M, int N, int K, int relu, int nz,
                         long sA, long sW, long sB, long sRes, long sC)
{
    dim3 grid(N / 128, M / 128, nz);
    gemm_bf16_kernel<<<grid, 256, GSMEM>>>(
        (const __nv_bfloat16*)aHi, (const __nv_bfloat16*)aLo,
        (const __nv_bfloat16*)h_Whi + wElemOff, (const __nv_bfloat16*)h_Wlo + wElemOff,
        bias, res, C, oHi, oLo, M, N, K, relu, sA, sW, sB, sRes, sC);
}
static inline void gemmS(const float* A, const float* W, const float* bias,
                         const float* res, float* C, int M, int N, int K, int relu)
{
    dim3 grid((N + BN - 1)/BN, (M + BM - 1)/BM);
    gemm_kernel<<<grid, 256>>>(A, W, bias, res, C, M, N, K, relu);
}

extern "C" void kernel_launch(void* const* d_in, const int* in_sizes, int n_in,
                              void* d_out, int out_size)
{
    const float* image      = (const float*)d_in[0];
    const float* text_hidden= (const float*)d_in[1];
    const float* patch_ln_g = (const float*)d_in[2];
    const float* patch_ln_b = (const float*)d_in[3];
    const float* patch_w    = (const float*)d_in[4];
    const float* patch_b    = (const float*)d_in[5];
    const float* text_w     = (const float*)d_in[6];
    const float* text_b     = (const float*)d_in[7];
    const float* attn_in_w  = (const float*)d_in[8];
    const float* attn_in_b  = (const float*)d_in[9];
    const float* attn_out_w = (const float*)d_in[10];
    const float* attn_out_b = (const float*)d_in[11];
    const float* mlp_w1     = (const float*)d_in[12];
    const float* mlp_b1     = (const float*)d_in[13];
    const float* mlp_w2     = (const float*)d_in[14];
    const float* mlp_b2     = (const float*)d_in[15];
    const float* ln_gamma   = (const float*)d_in[16];
    const float* ln_beta    = (const float*)d_in[17];
    const float* fin_g      = (const float*)d_in[18];
    const float* fin_b      = (const float*)d_in[19];
    const float* cls_w1     = (const float*)d_in[20];
    const float* cls_b1     = (const float*)d_in[21];
    const float* cls_w2     = (const float*)d_in[22];
    const float* cls_b2     = (const float*)d_in[23];

    cudaFuncSetAttribute(gemm_bf16_kernel,
                         cudaFuncAttributeMaxDynamicSharedMemorySize, GSMEM);

    float *xp,*qkvp,*qp,*kvp,*featp,*clshp;
    cudaGetSymbolAddress((void**)&xp,    g_x);
    cudaGetSymbolAddress((void**)&qkvp,  g_qkv);
    cudaGetSymbolAddress((void**)&qp,    g_q);
    cudaGetSymbolAddress((void**)&kvp,   g_kv);
    cudaGetSymbolAddress((void**)&featp, g_feat);
    cudaGetSymbolAddress((void**)&clshp, g_clsh);
    cudaGetSymbolAddress((void**)&h_Ahi,  g_bfAhi);
    cudaGetSymbolAddress((void**)&h_Alo,  g_bfAlo);
    cudaGetSymbolAddress((void**)&h_A2hi, g_bfA2hi);
    cudaGetSymbolAddress((void**)&h_A2lo, g_bfA2lo);
    cudaGetSymbolAddress((void**)&h_Whi,  g_bfWhi);
    cudaGetSymbolAddress((void**)&h_Wlo,  g_bfWlo);

    float* x1p = xp;
    float* x2p = xp + (size_t)M_*E_;

    const float scale = 0.125f;  // 1/sqrt(64)
    dim3 sc_grid2(13, 13, 2*B_*H_);
    dim3 sc_grid1(13, 13, B_*H_);
    dim3 pv_grid2(7, 2*B_*H_);
    dim3 pv_grid1(7, B_*H_);
    int sm2 = (2*B_*H_*N_*32 + 127) / 128;
    int sm1 = (B_*H_*N_*32 + 127) / 128;

    // --- embedding ---
    patch_ln_kernel<<<M_, 256>>>(image, patch_ln_g, patch_ln_b, h_Ahi, h_Alo);
    splitTo(patch_w, h_Whi, h_Wlo, (size_t)E_*PD_);
    gemmT(h_Ahi, h_Alo, 0, patch_b, nullptr, x1p, nullptr, nullptr,
          M_, E_, PD_, 0, 1, 0,0,0,0,0);
    splitTo(text_hidden, h_Ahi, h_Alo, (size_t)M_*768);
    splitTo(text_w, h_Whi, h_Wlo, (size_t)E_*768);
    gemmT(h_Ahi, h_Alo, 0, text_b, nullptr, x2p, nullptr, nullptr,
          M_, E_, 768, 0, 1, 0,0,0,0,0);
    posadd_kernel<<<(2*M_*E_ + 255)/256, 256>>>();

    for (int l = 0; l < L_; l++) {
        const float* g0 = ln_gamma + (size_t)(l*2+0)*E_;
        const float* b0 = ln_beta  + (size_t)(l*2+0)*E_;
        const float* g1 = ln_gamma + (size_t)(l*2+1)*E_;
        const float* b1 = ln_beta  + (size_t)(l*2+1)*E_;

        // --- self-attention, both streams batched (z = stream) ---
        {
            const float* wi = attn_in_w  + (size_t)(l*3)*1536*E_;
            const float* bi = attn_in_b  + (size_t)(l*3)*1536;
            const float* wo = attn_out_w + (size_t)(l*3)*E_*E_;
            const float* bo = attn_out_b + (size_t)(l*3)*E_;
            ln_split_kernel<<<2*M_, 256>>>(xp, g0, b0, h_Ahi, h_Alo);
            splitTo(wi, h_Whi, h_Wlo, (size_t)2*1536*E_);
            gemmT(h_Ahi, h_Alo, 0, bi, nullptr, qkvp, nullptr, nullptr,
                  M_, 1536, E_, 0, 2,
                  (long)M_*E_, (long)1536*E_, 1536, 0, (long)M_*1536);
            scores_kernel<<<sc_grid2, 256>>>(qkvp, qkvp + E_, 1536, 1536,
                                             (long)M_*1536, (long)M_*1536, scale);
            softmax_kernel<<<sm2, 128>>>(2*B_*H_*N_);
            pv_kernel<<<pv_grid2, 256>>>(qkvp + 2*E_, 1536,
                                         (long)M_*1536, (long)M_*E_/2, h_A2hi, h_A2lo);
            splitTo(wo, h_Whi, h_Wlo, (size_t)2*E_*E_);
            // writes BOTH fp32 x and its bf16 split (consumed by guide attention)
            gemmT(h_A2hi, h_A2lo, 0, bo, xp, xp, h_Ahi, h_Alo,
                  M_, E_, E_, 0, 2,
                  (long)M_*E_, (long)E_*E_, E_, (long)M_*E_, (long)M_*E_);
        }

        // --- guide attention: q from x2, kv from x1, overwrites x1 ---
        {
            const float* wi = attn_in_w  + (size_t)(l*3+2)*1536*E_;
            const float* bi = attn_in_b  + (size_t)(l*3+2)*1536;
            const float* wo = attn_out_w + (size_t)(l*3+2)*E_*E_;
            const float* bo = attn_out_b + (size_t)(l*3+2)*E_;
            splitTo(wi, h_Whi, h_Wlo, (size_t)1536*E_);   // rows 0..511 Q, 512..1535 KV
            // x split already in h_Ahi/h_Alo from self-attn-out epilogue
            gemmT(h_Ahi + (size_t)M_*E_/2, h_Alo + (size_t)M_*E_/2, 0,
                  bi, nullptr, qp, nullptr, nullptr,
                  M_, E_, E_, 0, 1, 0,0,0,0,0);
            gemmT(h_Ahi, h_Alo, (long)E_*E_, bi + E_, nullptr, kvp, nullptr, nullptr,
                  M_, 2*E_, E_, 0, 1, 0,0,0,0,0);
            scores_kernel<<<sc_grid1, 256>>>(qp, kvp, E_, 2*E_, 0, 0, scale);
            softmax_kernel<<<sm1, 128>>>(B_*H_*N_);
            pv_kernel<<<pv_grid1, 256>>>(kvp + E_, 2*E_, 0, 0, h_A2hi, h_A2lo);
            splitTo(wo, h_Whi, h_Wlo, (size_t)E_*E_);
            gemmT(h_A2hi, h_A2lo, 0, bo, nullptr, x1p, nullptr, nullptr,
                  M_, E_, E_, 0, 1, 0,0,0,0,0);
        }

        // --- MLP, both streams in one M=12544 GEMM (shared weights) ---
        {
            const float* w1  = mlp_w1 + (size_t)l*4*E_*E_;
            const float* bb1 = mlp_b1 + (size_t)l*4*E_;
            const float* w2  = mlp_w2 + (size_t)l*E_*4*E_;
            const float* bb2 = mlp_b2 + (size_t)l*E_;
            ln_split_kernel<<<2*M_, 256>>>(xp, g1, b1, h_Ahi, h_Alo);
            splitTo(w1, h_Whi, h_Wlo, (size_t)4*E_*E_);
            // relu hidden written directly as bf16 split (no fp32 round trip)
            gemmT(h_Ahi, h_Alo, 0, bb1, nullptr, nullptr, h_A2hi, h_A2lo,
                  2*M_, 4*E_, E_, 1, 1, 0,0,0,0,0);
            splitTo(w2, h_Whi, h_Wlo, (size_t)E_*4*E_);
            gemmT(h_A2hi, h_A2lo, 0, bb2, xp, xp, nullptr, nullptr,
                  2*M_, E_, 4*E_, 0, 1, 0,0,0,0,0);
        }
    }

    // --- head (tiny; SIMT path) ---
    final_feat_kernel<<<64, 256>>>(fin_g, fin_b);
    gemmS(featp, cls_w1, cls_b1, nullptr, clshp, B_, 4*E_, 2*E_, 1);
    gemmS(clshp, cls_w2, cls_b2, nullptr, (float*)d_out, B_, NCLS_, 4*E_, 0);
}

// round 15
// speedup vs baseline: 1.3833x; 1.3833x over previous
#include <cuda_runtime.h>
#include <cuda_bf16.h>
#include <math.h>
#include <stdint.h>

#define B_   32
#define N_   196
#define E_   512
#define H_   8
#define HD_  64
#define L_   4
#define M_   (B_*N_)          // 6272 tokens
#define PD_  3840             // patch dim
#define NCLS_ 101
#define EPS_ 1e-5f

// ---------------- scratch (device globals; no cudaMalloc allowed) ------------
__device__ float g_x[2*M_*E_];
__device__ float g_feat[B_*2*E_];
__device__ float g_clsh[B_*4*E_];
// bf16 hi/lo split buffers (words = elems/2)
#define MAXA_W 12845056   // (12544*2048)/2
#define MAXW_W 983040     // (512*3840)/2  (largest weight: patch_w)
__device__ uint32_t g_bfAhi[MAXA_W];
__device__ uint32_t g_bfAlo[MAXA_W];
__device__ uint32_t g_bfA2hi[MAXA_W];
__device__ uint32_t g_bfA2lo[MAXA_W];
__device__ uint32_t g_bfWhi[MAXW_W];
__device__ uint32_t g_bfWlo[MAXW_W];
__device__ uint32_t g_bfOhi[2*M_*256];     // attention output split
__device__ uint32_t g_bfOlo[2*M_*256];
__device__ uint32_t g_bfQshi[M_*256];      // guide Q split
__device__ uint32_t g_bfQslo[M_*256];
__device__ uint32_t g_bfKVhi[M_*512];      // guide KV split
__device__ uint32_t g_bfKVlo[M_*512];

// ---------------- PTX helpers (base compute_100-safe) ------------------------
__device__ __forceinline__ uint32_t smem_u32(const void* p) {
    uint32_t a;
    asm("{ .reg .u64 t; cvta.to.shared.u64 t, %1; cvt.u32.u64 %0, t; }" : "=r"(a) : "l"(p));
    return a;
}
__device__ __forceinline__ void ldm_x4(uint32_t addr, uint32_t* r) {
    asm volatile("ldmatrix.sync.aligned.m8n8.x4.shared.b16 {%0,%1,%2,%3}, [%4];"
        : "=r"(r[0]), "=r"(r[1]), "=r"(r[2]), "=r"(r[3]) : "r"(addr));
}
__device__ __forceinline__ void ldm_x4_t(uint32_t addr, uint32_t* r) {
    asm volatile("ldmatrix.sync.aligned.m8n8.x4.trans.shared.b16 {%0,%1,%2,%3}, [%4];"
        : "=r"(r[0]), "=r"(r[1]), "=r"(r[2]), "=r"(r[3]) : "r"(addr));
}
__device__ __forceinline__ void mma16816(float* c, const uint32_t* a, const uint32_t* b) {
    asm volatile("mma.sync.aligned.m16n8k16.row.col.f32.bf16.bf16.f32 "
        "{%0,%1,%2,%3}, {%4,%5,%6,%7}, {%8,%9}, {%0,%1,%2,%3};"
        : "+f"(c[0]), "+f"(c[1]), "+f"(c[2]), "+f"(c[3])
        : "r"(a[0]), "r"(a[1]), "r"(a[2]), "r"(a[3]), "r"(b[0]), "r"(b[1]));
}
__device__ __forceinline__ void cp16(uint32_t dst, const void* src) {
    asm volatile("cp.async.ca.shared.global [%0], [%1], 16;" :: "r"(dst), "l"(src));
}
#define CP_COMMIT() asm volatile("cp.async.commit_group;" ::: "memory")

__device__ __forceinline__ uint32_t pack_bf(float a, float b) {
    __nv_bfloat16 x = __float2bfloat16(a), y = __float2bfloat16(b);
    return ((uint32_t)__bfloat16_as_ushort(y) << 16) | __bfloat16_as_ushort(x);
}
__device__ __forceinline__ void split2(float a, float b, uint32_t& hi, uint32_t& lo) {
    __nv_bfloat16 ha = __float2bfloat16(a), hb = __float2bfloat16(b);
    hi = ((uint32_t)__bfloat16_as_ushort(hb) << 16) | __bfloat16_as_ushort(ha);
    lo = pack_bf(a - __bfloat162float(ha), b - __bfloat162float(hb));
}
__device__ __forceinline__ void cvt_hilo(float4 v, uint32_t& hi0, uint32_t& hi1,
                                         uint32_t& lo0, uint32_t& lo1) {
    split2(v.x, v.y, hi0, lo0);
    split2(v.z, v.w, hi1, lo1);
}

// ---------------- split: fp32 -> bf16 hi + lo --------------------------------
__global__ void split_kernel(const float4* __restrict__ in,
                             uint2* __restrict__ hi, uint2* __restrict__ lo, long n4)
{
    long i = (long)blockIdx.x * blockDim.x + threadIdx.x;
    if (i >= n4) return;
    float4 v = in[i];
    uint32_t h0, h1, l0, l1;
    cvt_hilo(v, h0, h1, l0, l1);
    hi[i] = make_uint2(h0, h1);
    lo[i] = make_uint2(l0, l1);
}

// ======= bf16 tensor-core GEMM: CTA 128x128, warp 64x32, 2-stage, occ 2 ======
#define ROWB 80
#define HOFF 10240
#define OFF_AL (1*HOFF)
#define OFF_BH (2*HOFF)
#define OFF_BL (3*HOFF)
#define BUFB   (4*HOFF)
#define GSMEM  (2*BUFB)            // 81920 -> 2 CTAs/SM

__global__ __launch_bounds__(256, 2)
void gemm_bf16_kernel(const __nv_bfloat16* __restrict__ Ahi,
                      const __nv_bfloat16* __restrict__ Alo,
                      const __nv_bfloat16* __restrict__ Bhi,
                      const __nv_bfloat16* __restrict__ Blo,
                      const float* __restrict__ bias,
                      const float* __restrict__ res,
                      float* __restrict__ C,
                      uint32_t* __restrict__ outHi,
                      uint32_t* __restrict__ outLo,
                      int M, int N, int K, int relu,
                      long sA, long sW, long sB, long sRes, long sC)
{
    int z = blockIdx.z;
    Ahi += (size_t)z * sA;  Alo += (size_t)z * sA;
    Bhi += (size_t)z * sW;  Blo += (size_t)z * sW;
    bias += (size_t)z * sB;
    if (res) res += (size_t)z * sRes;
    if (C)   C   += (size_t)z * sC;
    if (outHi) { outHi += (size_t)z * (sC >> 1); outLo += (size_t)z * (sC >> 1); }

    extern __shared__ char sm[];
    const uint32_t sbase = smem_u32(sm);
    const int tid = threadIdx.x, wid = tid >> 5, lane = tid & 31;
    const int m0 = blockIdx.y * 128, n0 = blockIdx.x * 128;
    const int wm = wid >> 2, wn = wid & 3;

    float acc[4][4][4];
#pragma unroll
    for (int i = 0; i < 4; i++)
#pragma unroll
        for (int j = 0; j < 4; j++)
#pragma unroll
            for (int r = 0; r < 4; r++) acc[i][j][r] = 0.f;

    const int c0row = tid >> 2, c0c = tid & 3;
    const int c1row = (tid + 256) >> 2, c1c = (tid + 256) & 3;

    auto issue = [&](int s, int buf) {
        uint32_t base = sbase + buf * BUFB;
        long kb = (long)s * 32;
        cp16(base + c0row * ROWB + c0c * 16,          Ahi + (size_t)(m0 + c0row) * K + kb + c0c * 8);
        cp16(base + OFF_AL + c0row * ROWB + c0c * 16, Alo + (size_t)(m0 + c0row) * K + kb + c0c * 8);
        cp16(base + c1row * ROWB + c1c * 16,          Ahi + (size_t)(m0 + c1row) * K + kb + c1c * 8);
        cp16(base + OFF_AL + c1row * ROWB + c1c * 16, Alo + (size_t)(m0 + c1row) * K + kb + c1c * 8);
        cp16(base + OFF_BH + c0row * ROWB + c0c * 16, Bhi + (size_t)(n0 + c0row) * K + kb + c0c * 8);
        cp16(base + OFF_BL + c0row * ROWB + c0c * 16, Blo + (size_t)(n0 + c0row) * K + kb + c0c * 8);
        cp16(base + OFF_BH + c1row * ROWB + c1c * 16, Bhi + (size_t)(n0 + c1row) * K + kb + c1c * 8);
        cp16(base + OFF_BL + c1row * ROWB + c1c * 16, Blo + (size_t)(n0 + c1row) * K + kb + c1c * 8);
    };

    const uint32_t aR = (uint32_t)(wm * 64 + (lane & 7) + ((lane >> 3) & 1) * 8);
    const uint32_t aC = (uint32_t)((lane >> 4) * 8);
    const uint32_t bR = (uint32_t)(wn * 32 + (lane & 7) + (lane >> 4) * 8);
    const uint32_t bC = (uint32_t)(((lane >> 3) & 1) * 8);

    auto compute = [&](int buf) {
        uint32_t bb = sbase + buf * BUFB;
#pragma unroll
        for (int kk = 0; kk < 32; kk += 16) {
            uint32_t ah[4][4], al[4][4], bh[2][4], bl[2][4];
#pragma unroll
            for (int mt = 0; mt < 4; mt++) {
                uint32_t off = (aR + mt * 16) * ROWB + (kk + aC) * 2;
                ldm_x4(bb + off, ah[mt]);
                ldm_x4(bb + OFF_AL + off, al[mt]);
            }
#pragma unroll
            for (int nt2 = 0; nt2 < 2; nt2++) {
                uint32_t off = (bR + nt2 * 16) * ROWB + (kk + bC) * 2;
                ldm_x4(bb + OFF_BH + off, bh[nt2]);
                ldm_x4(bb + OFF_BL + off, bl[nt2]);
            }
#pragma unroll
            for (int mt = 0; mt < 4; mt++)
#pragma unroll
                for (int nt = 0; nt < 4; nt++) {
                    const uint32_t* bhp = &bh[nt >> 1][(nt & 1) * 2];
                    const uint32_t* blp = &bl[nt >> 1][(nt & 1) * 2];
                    mma16816(acc[mt][nt], ah[mt], bhp);
                    mma16816(acc[mt][nt], ah[mt], blp);
                    mma16816(acc[mt][nt], al[mt], bhp);
                }
        }
    };

    const int nslab = K >> 5;
    issue(0, 0); CP_COMMIT();
    for (int s = 0; s < nslab; s++) {
        if (s + 1 < nslab) { issue(s + 1, (s + 1) & 1); CP_COMMIT(); }
        if (s + 1 < nslab) asm volatile("cp.async.wait_group 1;" ::: "memory");
        else               asm volatile("cp.async.wait_group 0;" ::: "memory");
        __syncthreads();
        compute(s & 1);
        __syncthreads();
    }

#pragma unroll
    for (int mt = 0; mt < 4; mt++)
#pragma unroll
        for (int nt = 0; nt < 4; nt++) {
            int m = m0 + wm * 64 + mt * 16 + (lane >> 2);
            int n = n0 + wn * 32 + nt * 8 + (lane & 3) * 2;
            float b0 = bias[n], b1 = bias[n + 1];
#pragma unroll
            for (int half = 0; half < 2; half++) {
                int mm = m + half * 8;
                float v0 = acc[mt][nt][half * 2]     + b0;
                float v1 = acc[mt][nt][half * 2 + 1] + b1;
                if (res) {
                    float2 r2 = *reinterpret_cast<const float2*>(res + (size_t)mm * N + n);
                    v0 += r2.x; v1 += r2.y;
                }
                if (relu) { v0 = fmaxf(v0, 0.f); v1 = fmaxf(v1, 0.f); }
                if (C)
                    *reinterpret_cast<float2*>(C + (size_t)mm * N + n) = make_float2(v0, v1);
                if (outHi) {
                    uint32_t hw, lw;
                    split2(v0, v1, hw, lw);
                    size_t wi = (size_t)mm * (N >> 1) + (n >> 1);
                    outHi[wi] = hw; outLo[wi] = lw;
                }
            }
        }
}

// ======== fused attention: S=QK^T (split mma), softmax, O=PV (split mma) =====
// One CTA per (z, b, h). Q processed in 4 tiles of 64 rows. All bf16 hi/lo.
#define AK_ROW 144
#define A_KHI 0
#define A_KLO 34560
#define A_VHI 69120
#define A_VLO 103680
#define A_QHI 138240
#define A_QLO 147456
#define A_PROW 464
#define A_PHI 156672
#define A_PLO 186368
#define A_PMAX 216064
#define A_PSUM 217088
#define ATT_SMEM 218112

__global__ __launch_bounds__(256, 1)
void attn_kernel(const uint32_t* __restrict__ Qhi, const uint32_t* __restrict__ Qlo,
                 int qRowW, long qZW,
                 const uint32_t* __restrict__ Khi, const uint32_t* __restrict__ Klo,
                 int kRowW, long kZW,
                 const uint32_t* __restrict__ Vhi, const uint32_t* __restrict__ Vlo,
                 int vRowW, long vZW,
                 uint32_t* __restrict__ outHi, uint32_t* __restrict__ outLo, long outZW)
{
    extern __shared__ char sm[];
    const uint32_t sbase = smem_u32(sm);
    const int tid = threadIdx.x, wid = tid >> 5, lane = tid & 31;
    const int zz = blockIdx.x;
    const int z = zz >> 8, bh = zz & 255;
    const int b = bh >> 3, h = bh & 7;
    const int wm = wid >> 2, wn = wid & 3;   // S: m 2x32... S uses wm in {0,1} x wn {0..3}
    float* pmax = (float*)(sm + A_PMAX);     // [4][64]
    float* psum = (float*)(sm + A_PSUM);     // [4][64]

    // ---- zero pad rows 196..239 of K/V (both halves) ----
    const uint4 z4 = make_uint4(0,0,0,0);
    for (int i = tid; i < 396; i += 256) {
        int r = 196 + i / 9, c = (i % 9) * 16;
        *(uint4*)(sm + A_KHI + r*AK_ROW + c) = z4;
        *(uint4*)(sm + A_KLO + r*AK_ROW + c) = z4;
        *(uint4*)(sm + A_VHI + r*AK_ROW + c) = z4;
        *(uint4*)(sm + A_VLO + r*AK_ROW + c) = z4;
    }
    // ---- load K and V (196 rows x 64 elems, hi+lo) via cp.async ----
    for (int i = tid; i < 1568; i += 256) {
        int r = i >> 3, c = i & 7;
        size_t goff = (size_t)z * kZW + (size_t)(b*N_ + r) * kRowW + h*32 + c*4;
        cp16(sbase + A_KHI + r*AK_ROW + c*16, Khi + goff);
        cp16(sbase + A_KLO + r*AK_ROW + c*16, Klo + goff);
        size_t voff = (size_t)z * vZW + (size_t)(b*N_ + r) * vRowW + h*32 + c*4;
        cp16(sbase + A_VHI + r*AK_ROW + c*16, Vhi + voff);
        cp16(sbase + A_VLO + r*AK_ROW + c*16, Vlo + voff);
    }
    CP_COMMIT();
    asm volatile("cp.async.wait_group 0;" ::: "memory");
    __syncthreads();

    const uint32_t aRowLane = (uint32_t)((lane & 7) + ((lane >> 3) & 1) * 8);
    const uint32_t aColLane = (uint32_t)((lane >> 4) * 8);
    const uint32_t bRowLane = (uint32_t)((lane & 7) + (lane >> 4) * 8);
    const uint32_t bColLane = (uint32_t)(((lane >> 3) & 1) * 8);

    for (int qt = 0; qt < 4; qt++) {
        int q0 = qt * 64;
        __syncthreads();   // previous tile fully consumed (PV reads done)
        // ---- load Q tile (64 rows, hi+lo), zero invalid rows ----
        for (int i = tid; i < 512; i += 256) {
            int r = i >> 3, c = i & 7;
            int q = q0 + r;
            if (q < N_) {
                size_t goff = (size_t)z * qZW + (size_t)(b*N_ + q) * qRowW + h*32 + c*4;
                cp16(sbase + A_QHI + r*AK_ROW + c*16, Qhi + goff);
                cp16(sbase + A_QLO + r*AK_ROW + c*16, Qlo + goff);
            } else {
                *(uint4*)(sm + A_QHI + r*AK_ROW + c*16) = z4;
                *(uint4*)(sm + A_QLO + r*AK_ROW + c*16) = z4;
            }
        }
        CP_COMMIT();
        asm volatile("cp.async.wait_group 0;" ::: "memory");
        __syncthreads();

        // ---- S = Q @ K^T : warp tile m32 x n56, k=64 ----
        float sacc[2][7][4];
#pragma unroll
        for (int i = 0; i < 2; i++)
#pragma unroll
            for (int j = 0; j < 7; j++)
#pragma unroll
                for (int r = 0; r < 4; r++) sacc[i][j][r] = 0.f;
#pragma unroll
        for (int ks = 0; ks < 4; ks++) {
            int koff = ks * 16;
            uint32_t ah[2][4], al[2][4], bh4[4][4], bl4[4][4];
#pragma unroll
            for (int mf = 0; mf < 2; mf++) {
                uint32_t off = (wm*32 + mf*16 + aRowLane) * AK_ROW + (koff + aColLane) * 2;
                ldm_x4(sbase + A_QHI + off, ah[mf]);
                ldm_x4(sbase + A_QLO + off, al[mf]);
            }
#pragma unroll
            for (int g = 0; g < 4; g++) {
                uint32_t off = (wn*56 + g*16 + bRowLane) * AK_ROW + (koff + bColLane) * 2;
                ldm_x4(sbase + A_KHI + off, bh4[g]);
                ldm_x4(sbase + A_KLO + off, bl4[g]);
            }
#pragma unroll
            for (int mf = 0; mf < 2; mf++)
#pragma unroll
                for (int nf = 0; nf < 7; nf++) {
                    const uint32_t* bhp = &bh4[nf >> 1][(nf & 1) * 2];
                    const uint32_t* blp = &bl4[nf >> 1][(nf & 1) * 2];
                    mma16816(sacc[mf][nf], ah[mf], bhp);
                    mma16816(sacc[mf][nf], ah[mf], blp);
                    mma16816(sacc[mf][nf], al[mf], bhp);
                }
        }

        // ---- softmax (scale, mask, row max/sum across 4 n-warps) ----
        float rmx[2][2] = {{-1e30f,-1e30f},{-1e30f,-1e30f}};
#pragma unroll
        for (int mf = 0; mf < 2; mf++)
#pragma unroll
            for (int nf = 0; nf < 7; nf++)
#pragma unroll
                for (int r = 0; r < 4; r++) {
                    int ncol = wn*56 + nf*8 + 2*(lane & 3) + (r & 1);
                    float v = sacc[mf][nf][r] * 0.125f;
                    if (ncol >= N_) v = -1e30f;
                    sacc[mf][nf][r] = v;
                    int rp = r >> 1;
                    rmx[mf][rp] = fmaxf(rmx[mf][rp], v);
                }
#pragma unroll
        for (int mf = 0; mf < 2; mf++)
#pragma unroll
            for (int rp = 0; rp < 2; rp++) {
                float v = rmx[mf][rp];
                v = fmaxf(v, __shfl_xor_sync(0xffffffffu, v, 1));
                v = fmaxf(v, __shfl_xor_sync(0xffffffffu, v, 2));
                rmx[mf][rp] = v;
                if ((lane & 3) == 0)
                    pmax[wn*64 + wm*32 + mf*16 + (lane >> 2) + rp*8] = v;
            }
        __syncthreads();
        float rsum[2][2] = {{0.f,0.f},{0.f,0.f}};
#pragma unroll
        for (int mf = 0; mf < 2; mf++)
#pragma unroll
            for (int rp = 0; rp < 2; rp++) {
                int row = wm*32 + mf*16 + (lane >> 2) + rp*8;
                float m0 = fmaxf(fmaxf(pmax[row], pmax[64+row]),
                                 fmaxf(pmax[128+row], pmax[192+row]));
                rmx[mf][rp] = m0;
            }
#pragma unroll
        for (int mf = 0; mf < 2; mf++)
#pragma unroll
            for (int nf = 0; nf < 7; nf++)
#pragma unroll
                for (int r = 0; r < 4; r++) {
                    float e = __expf(sacc[mf][nf][r] - rmx[mf][r >> 1]);
                    sacc[mf][nf][r] = e;
                    rsum[mf][r >> 1] += e;
                }
#pragma unroll
        for (int mf = 0; mf < 2; mf++)
#pragma unroll
            for (int rp = 0; rp < 2; rp++) {
                float v = rsum[mf][rp];
                v += __shfl_xor_sync(0xffffffffu, v, 1);
                v += __shfl_xor_sync(0xffffffffu, v, 2);
                if ((lane & 3) == 0)
                    psum[wn*64 + wm*32 + mf*16 + (lane >> 2) + rp*8] = v;
            }
        // ---- store unnormalized P (bf16 split) ----
#pragma unroll
        for (int mf = 0; mf < 2; mf++)
#pragma unroll
            for (int nf = 0; nf < 7; nf++) {
                int row = wm*32 + mf*16 + (lane >> 2);
                int col = wn*56 + nf*8 + 2*(lane & 3);
                uint32_t hw, lw;
                split2(sacc[mf][nf][0], sacc[mf][nf][1], hw, lw);
                *(uint32_t*)(sm + A_PHI + row*A_PROW + col*2) = hw;
                *(uint32_t*)(sm + A_PLO + row*A_PROW + col*2) = lw;
                split2(sacc[mf][nf][2], sacc[mf][nf][3], hw, lw);
                *(uint32_t*)(sm + A_PHI + (row+8)*A_PROW + col*2) = hw;
                *(uint32_t*)(sm + A_PLO + (row+8)*A_PROW + col*2) = lw;
            }
        __syncthreads();

        // ---- O = P @ V : warp tile m32 x n16, k=224 ----
        float oacc[2][2][4];
#pragma unroll
        for (int i = 0; i < 2; i++)
#pragma unroll
            for (int j = 0; j < 2; j++)
#pragma unroll
                for (int r = 0; r < 4; r++) oacc[i][j][r] = 0.f;
        const uint32_t vRowT = (uint32_t)(((lane >> 3) & 1) * 8 + (lane & 7));
        const uint32_t vColT = (uint32_t)(wn*16 + (lane >> 4) * 8);
#pragma unroll
        for (int ks = 0; ks < 14; ks++) {
            int koff = ks * 16;
            uint32_t pah[2][4], pal[2][4], vbh[4], vbl[4];
#pragma unroll
            for (int mf = 0; mf < 2; mf++) {
                uint32_t off = (wm*32 + mf*16 + aRowLane) * A_PROW + (koff + aColLane) * 2;
                ldm_x4(sbase + A_PHI + off, pah[mf]);
                ldm_x4(sbase + A_PLO + off, pal[mf]);
            }
            {
                uint32_t off = (koff + vRowT) * AK_ROW + vColT * 2;
                ldm_x4_t(sbase + A_VHI + off, vbh);
                ldm_x4_t(sbase + A_VLO + off, vbl);
            }
#pragma unroll
            for (int mf = 0; mf < 2; mf++)
#pragma unroll
                for (int ng = 0; ng < 2; ng++) {
                    mma16816(oacc[mf][ng], pah[mf], &vbh[ng*2]);
                    mma16816(oacc[mf][ng], pah[mf], &vbl[ng*2]);
                    mma16816(oacc[mf][ng], pal[mf], &vbh[ng*2]);
                }
        }
        // ---- epilogue: normalize + write bf16 split ----
#pragma unroll
        for (int mf = 0; mf < 2; mf++)
#pragma unroll
            for (int ng = 0; ng < 2; ng++) {
                int col = wn*16 + ng*8 + 2*(lane & 3);
#pragma unroll
                for (int rp = 0; rp < 2; rp++) {
                    int row = wm*32 + mf*16 + (lane >> 2) + rp*8;
                    int q = q0 + row;
                    if (q < N_) {
                        float s0 = psum[row] + psum[64+row] + psum[128+row] + psum[192+row];
                        float inv = 1.f / s0;
                        float v0 = oacc[mf][ng][rp*2]     * inv;
                        float v1 = oacc[mf][ng][rp*2 + 1] * inv;
                        uint32_t hw, lw;
                        split2(v0, v1, hw, lw);
                        size_t wi = (size_t)z * outZW + (size_t)(b*N_ + q) * 256 + h*32 + (col >> 1);
                        outHi[wi] = hw; outLo[wi] = lw;
                    }
                }
            }
    }
}

// ------- fallback SIMT GEMM (head; any shape) --------------------------------
#define BM 128
#define BN 64
#define BK 16
__global__ __launch_bounds__(256, 2)
void gemm_kernel(const float* __restrict__ A,
                 const float* __restrict__ W,
                 const float* __restrict__ bias,
                 const float* __restrict__ res,
                 float* __restrict__ C,
                 int M, int N, int K, int relu)
{
    __shared__ float As[BK][BM+4];
    __shared__ float Ws[BK][BN+4];
    int tid = threadIdx.x;
    int tx = tid & 15, ty = tid >> 4;
    int m0 = blockIdx.y * BM, n0 = blockIdx.x * BN;
    float acc[8][4];
#pragma unroll
    for (int i = 0; i < 8; i++)
#pragma unroll
        for (int j = 0; j < 4; j++) acc[i][j] = 0.f;

    for (int k0 = 0; k0 < K; k0 += BK) {
#pragma unroll
        for (int t = 0; t < 2; t++) {
            int f = tid + t * 256;
            int r = f >> 2, kq = (f & 3) << 2;
            int m = m0 + r;
            float4 v = make_float4(0.f,0.f,0.f,0.f);
            if (m < M) v = *reinterpret_cast<const float4*>(A + (size_t)m*K + k0 + kq);
            As[kq][r]   = v.x; As[kq+1][r] = v.y;
            As[kq+2][r] = v.z; As[kq+3][r] = v.w;
        }
        {
            int r = tid >> 2, kq = (tid & 3) << 2;
            int n = n0 + r;
            float4 v = make_float4(0.f,0.f,0.f,0.f);
            if (n < N) v = *reinterpret_cast<const float4*>(W + (size_t)n*K + k0 + kq);
            Ws[kq][r]   = v.x; Ws[kq+1][r] = v.y;
            Ws[kq+2][r] = v.z; Ws[kq+3][r] = v.w;
        }
        __syncthreads();
#pragma unroll
        for (int kk = 0; kk < BK; kk++) {
            float a[8], b[4];
            *reinterpret_cast<float4*>(a)   = *reinterpret_cast<const float4*>(&As[kk][ty*8]);
            *reinterpret_cast<float4*>(a+4) = *reinterpret_cast<const float4*>(&As[kk][ty*8+4]);
            *reinterpret_cast<float4*>(b)   = *reinterpret_cast<const float4*>(&Ws[kk][tx*4]);
#pragma unroll
            for (int i = 0; i < 8; i++)
#pragma unroll
                for (int j = 0; j < 4; j++)
                    acc[i][j] += a[i]*b[j];
        }
        __syncthreads();
    }
#pragma unroll
    for (int i = 0; i < 8; i++) {
        int m = m0 + ty*8 + i;
        if (m >= M) continue;
#pragma unroll
        for (int j = 0; j < 4; j++) {
            int n = n0 + tx*4 + j;
            if (n >= N) continue;
            float v = acc[i][j] + bias[n];
            if (res) v += res[(size_t)m*N + n];
            if (relu) v = fmaxf(v, 0.f);
            C[(size_t)m*N + n] = v;
        }
    }
}

// ---------------- LayerNorm over 512 -> bf16 hi/lo split ---------------------
__global__ void ln_split_kernel(const float* __restrict__ x,
                                const float* __restrict__ g,
                                const float* __restrict__ b,
                                uint32_t* __restrict__ hi,
                                uint32_t* __restrict__ lo)
{
    int row = blockIdx.x;
    const float* xr = x + (size_t)row * E_;
    int tid = threadIdx.x;
    float2 v = *reinterpret_cast<const float2*>(xr + 2*tid);
    float s  = v.x + v.y;
    float ss = v.x*v.x + v.y*v.y;
#pragma unroll
    for (int o = 16; o > 0; o >>= 1) {
        s  += __shfl_xor_sync(0xffffffffu, s,  o);
        ss += __shfl_xor_sync(0xffffffffu, ss, o);
    }
    __shared__ float sh[16];
    int w = tid >> 5, lane = tid & 31;
    if (lane == 0) { sh[w] = s; sh[8+w] = ss; }
    __syncthreads();
    if (tid == 0) {
        float a = 0.f, c = 0.f;
        for (int i = 0; i < 8; i++) { a += sh[i]; c += sh[8+i]; }
        sh[0] = a; sh[8] = c;
    }
    __syncthreads();
    float mean = sh[0] * (1.f/E_);
    float var  = sh[8] * (1.f/E_) - mean*mean;
    float rs = rsqrtf(var + EPS_);
    float2 gg = *reinterpret_cast<const float2*>(g + 2*tid);
    float2 bb = *reinterpret_cast<const float2*>(b + 2*tid);
    float y0 = (v.x - mean) * rs * gg.x + bb.x;
    float y1 = (v.y - mean) * rs * gg.y + bb.y;
    uint32_t hw, lw;
    split2(y0, y1, hw, lw);
    size_t wi = (size_t)row * 256 + tid;
    hi[wi] = hw; lo[wi] = lw;
}

// ------- shifted-patch gather + LN(3840) -> bf16 hi/lo split -----------------
__global__ void patch_ln_kernel(const float* __restrict__ image,
                                const float* __restrict__ g,
                                const float* __restrict__ bb,
                                uint32_t* __restrict__ hi,
                                uint32_t* __restrict__ lo)
{
    __shared__ float buf[PD_];
    __shared__ float sh[16];
    int bn = blockIdx.x;
    int b  = bn / N_, n = bn % N_;
    int ph = n / 14, pw = n % 14;
    int tid = threadIdx.x;

    float s = 0.f, ss = 0.f;
    for (int d = tid; d < PD_; d += 256) {
        int c  = d % 15, t = d / 15;
        int p2 = t % 16, p1 = t / 16;
        int sh_idx = c / 3, ch = c % 3;
        int row = ph*16 + p1, col = pw*16 + p2;
        if      (sh_idx == 1) col -= 1;
        else if (sh_idx == 2) col += 1;
        else if (sh_idx == 3) row -= 1;
        else if (sh_idx == 4) row += 1;
        float v = 0.f;
        if (row >= 0 && row < 224 && col >= 0 && col < 224)
            v = image[(((size_t)b*3 + ch)*224 + row)*224 + col];
        buf[d] = v;
        s += v; ss += v*v;
    }
#pragma unroll
    for (int o = 16; o > 0; o >>= 1) {
        s  += __shfl_xor_sync(0xffffffffu, s,  o);
        ss += __shfl_xor_sync(0xffffffffu, ss, o);
    }
    int w = tid >> 5, lane = tid & 31;
    if (lane == 0) { sh[w] = s; sh[8+w] = ss; }
    __syncthreads();
    if (tid == 0) {
        float a = 0.f, c = 0.f;
        for (int i = 0; i < 8; i++) { a += sh[i]; c += sh[8+i]; }
        sh[0] = a; sh[8] = c;
    }
    __syncthreads();
    float mean = sh[0] * (1.f/PD_);
    float var  = sh[8] * (1.f/PD_) - mean*mean;
    float rs = rsqrtf(var + EPS_);
    uint32_t* hrow = hi + (size_t)bn * (PD_/2);
    uint32_t* lrow = lo + (size_t)bn * (PD_/2);
    for (int d = 2*tid; d < PD_; d += 512) {
        float y0 = (buf[d]   - mean) * rs * g[d]   + bb[d];
        float y1 = (buf[d+1] - mean) * rs * g[d+1] + bb[d+1];
        uint32_t hw, lw;
        split2(y0, y1, hw, lw);
        hrow[d >> 1] = hw; lrow[d >> 1] = lw;
    }
}

// ---------------- positional add (buggy batch-indexed sinusoid, per ref) -----
__global__ void posadd_kernel()
{
    int idx = blockIdx.x * 256 + threadIdx.x;
    if (idx >= 2*M_*E_) return;
    int e = idx & (E_-1);
    int stream_rem = idx % (M_*E_);
    int b = stream_rem / (N_*E_);
    float p = (float)(b + 1);
    int i = e & 255;
    float f = expf(-(float)i * (9.210340371976184f / 255.0f));
    float ang = p * f;
    float v = (e < 256) ? sinf(ang) : cosf(ang);
    g_x[idx] += v;
}

// ---------------- final LN of last token -> feat (B, 2E) ---------------------
__global__ void final_feat_kernel(const float* __restrict__ g,
                                  const float* __restrict__ b)
{
    int s = blockIdx.x >> 5;
    int bb = blockIdx.x & 31;
    const float* src = g_x + ((size_t)s*M_ + bb*N_ + (N_-1)) * E_;
    int tid = threadIdx.x;
    float v0 = src[tid], v1 = src[tid + 256];
    float ssum = v0 + v1, sq = v0*v0 + v1*v1;
#pragma unroll
    for (int o = 16; o > 0; o >>= 1) {
        ssum += __shfl_xor_sync(0xffffffffu, ssum, o);
        sq   += __shfl_xor_sync(0xffffffffu, sq,   o);
    }
    __shared__ float sh[16];
    int w = tid >> 5, lane = tid & 31;
    if (lane == 0) { sh[w] = ssum; sh[8+w] = sq; }
    __syncthreads();
    if (tid == 0) {
        float a = 0.f, c = 0.f;
        for (int i = 0; i < 8; i++) { a += sh[i]; c += sh[8+i]; }
        sh[0] = a; sh[8] = c;
    }
    __syncthreads();
    float mean = sh[0] * (1.f/E_);
    float var  = sh[8] * (1.f/E_) - mean*mean;
    float rs = rsqrtf(var + EPS_);
    float* dst = g_feat + (size_t)bb * (2*E_) + s*E_;
    dst[tid]       = (v0 - mean) * rs * g[tid]       + b[tid];
    dst[tid + 256] = (v1 - mean) * rs * g[tid + 256] + b[tid + 256];
}

// ---------------- host-side orchestration ------------------------------------
static uint32_t *h_Ahi, *h_Alo, *h_A2hi, *h_A2lo, *h_Whi, *h_Wlo;
static uint32_t *h_Ohi, *h_Olo, *h_Qshi, *h_Qslo, *h_KVhi, *h_KVlo;

static inline void splitTo(const float* src, uint32_t* hi, uint32_t* lo, size_t n)
{
    long n4 = (long)(n >> 2);
    split_kernel<<<(unsigned)((n4 + 255) / 256), 256>>>(
        (const float4*)src, (uint2*)hi, (uint2*)lo, n4);
}
static inline void gemmT(const uint32_t* aHi, const uint32_t* aLo, long wElemOff,
                         const float* bias, const float* res, float* C,
                         uint32_t* oHi, uint32_t* oLo,
                         int M, int N, int K, int relu, int nz,
                         long sA, long sW, long sB, long sRes, long sC)
{
    dim3 grid(N / 128, M / 128, nz);
    gemm_bf16_kernel<<<grid, 256, GSMEM>>>(
        (const __nv_bfloat16*)aHi, (const __nv_bfloat16*)aLo,
        (const __nv_bfloat16*)h_Whi + wElemOff, (const __nv_bfloat16*)h_Wlo + wElemOff,
        bias, res, C, oHi, oLo, M, N, K, relu, sA, sW, sB, sRes, sC);
}
static inline void gemmS(const float* A, const float* W, const float* bias,
                         const float* res, float* C, int M, int N, int K, int relu)
{
    dim3 grid((N + BN - 1)/BN, (M + BM - 1)/BM);
    gemm_kernel<<<grid, 256>>>(A, W, bias, res, C, M, N, K, relu);
}

extern "C" void kernel_launch(void* const* d_in, const int* in_sizes, int n_in,
                              void* d_out, int out_size)
{
    const float* image      = (const float*)d_in[0];
    const float* text_hidden= (const float*)d_in[1];
    const float* patch_ln_g = (const float*)d_in[2];
    const float* patch_ln_b = (const float*)d_in[3];
    const float* patch_w    = (const float*)d_in[4];
    const float* patch_b    = (const float*)d_in[5];
    const float* text_w     = (const float*)d_in[6];
    const float* text_b     = (const float*)d_in[7];
    const float* attn_in_w  = (const float*)d_in[8];
    const float* attn_in_b  = (const float*)d_in[9];
    const float* attn_out_w = (const float*)d_in[10];
    const float* attn_out_b = (const float*)d_in[11];
    const float* mlp_w1     = (const float*)d_in[12];
    const float* mlp_b1     = (const float*)d_in[13];
    const float* mlp_w2     = (const float*)d_in[14];
    const float* mlp_b2     = (const float*)d_in[15];
    const float* ln_gamma   = (const float*)d_in[16];
    const float* ln_beta    = (const float*)d_in[17];
    const float* fin_g      = (const float*)d_in[18];
    const float* fin_b      = (const float*)d_in[19];
    const float* cls_w1     = (const float*)d_in[20];
    const float* cls_b1     = (const float*)d_in[21];
    const float* cls_w2     = (const float*)d_in[22];
    const float* cls_b2     = (const float*)d_in[23];

    cudaFuncSetAttribute(gemm_bf16_kernel,
                         cudaFuncAttributeMaxDynamicSharedMemorySize, GSMEM);
    cudaFuncSetAttribute(attn_kernel,
                         cudaFuncAttributeMaxDynamicSharedMemorySize, ATT_SMEM);

    float *xp,*featp,*clshp;
    cudaGetSymbolAddress((void**)&xp,    g_x);
    cudaGetSymbolAddress((void**)&featp, g_feat);
    cudaGetSymbolAddress((void**)&clshp, g_clsh);
    cudaGetSymbolAddress((void**)&h_Ahi,  g_bfAhi);
    cudaGetSymbolAddress((void**)&h_Alo,  g_bfAlo);
    cudaGetSymbolAddress((void**)&h_A2hi, g_bfA2hi);
    cudaGetSymbolAddress((void**)&h_A2lo, g_bfA2lo);
    cudaGetSymbolAddress((void**)&h_Whi,  g_bfWhi);
    cudaGetSymbolAddress((void**)&h_Wlo,  g_bfWlo);
    cudaGetSymbolAddress((void**)&h_Ohi,  g_bfOhi);
    cudaGetSymbolAddress((void**)&h_Olo,  g_bfOlo);
    cudaGetSymbolAddress((void**)&h_Qshi, g_bfQshi);
    cudaGetSymbolAddress((void**)&h_Qslo, g_bfQslo);
    cudaGetSymbolAddress((void**)&h_KVhi, g_bfKVhi);
    cudaGetSymbolAddress((void**)&h_KVlo, g_bfKVlo);

    float* x1p = xp;

    // --- embedding ---
    patch_ln_kernel<<<M_, 256>>>(image, patch_ln_g, patch_ln_b, h_Ahi, h_Alo);
    splitTo(patch_w, h_Whi, h_Wlo, (size_t)E_*PD_);
    gemmT(h_Ahi, h_Alo, 0, patch_b, nullptr, x1p, nullptr, nullptr,
          M_, E_, PD_, 0, 1, 0,0,0,0,0);
    splitTo(text_hidden, h_Ahi, h_Alo, (size_t)M_*768);
    splitTo(text_w, h_Whi, h_Wlo, (size_t)E_*768);
    gemmT(h_Ahi, h_Alo, 0, text_b, nullptr, xp + (size_t)M_*E_, nullptr, nullptr,
          M_, E_, 768, 0, 1, 0,0,0,0,0);
    posadd_kernel<<<(2*M_*E_ + 255)/256, 256>>>();

    for (int l = 0; l < L_; l++) {
        const float* g0 = ln_gamma + (size_t)(l*2+0)*E_;
        const float* b0 = ln_beta  + (size_t)(l*2+0)*E_;
        const float* g1 = ln_gamma + (size_t)(l*2+1)*E_;
        const float* b1 = ln_beta  + (size_t)(l*2+1)*E_;

        // --- self-attention, both streams batched (z = stream) ---
        {
            const float* wi = attn_in_w  + (size_t)(l*3)*1536*E_;
            const float* bi = attn_in_b  + (size_t)(l*3)*1536;
            const float* wo = attn_out_w + (size_t)(l*3)*E_*E_;
            const float* bo = attn_out_b + (size_t)(l*3)*E_;
            ln_split_kernel<<<2*M_, 256>>>(xp, g0, b0, h_Ahi, h_Alo);
            splitTo(wi, h_Whi, h_Wlo, (size_t)2*1536*E_);
            gemmT(h_Ahi, h_Alo, 0, bi, nullptr, nullptr, h_A2hi, h_A2lo,
                  M_, 1536, E_, 0, 2,
                  (long)M_*E_, (long)1536*E_, 1536, 0, (long)M_*1536);
            attn_kernel<<<512, 256, ATT_SMEM>>>(
                h_A2hi,       h_A2lo,       768, (long)M_*768,
                h_A2hi + 256, h_A2lo + 256, 768, (long)M_*768,
                h_A2hi + 512, h_A2lo + 512, 768, (long)M_*768,
                h_Ohi, h_Olo, (long)M_*256);
            splitTo(wo, h_Whi, h_Wlo, (size_t)2*E_*E_);
            // writes fp32 x and its bf16 split (split consumed by guide attention)
            gemmT(h_Ohi, h_Olo, 0, bo, xp, xp, h_Ahi, h_Alo,
                  M_, E_, E_, 0, 2,
                  (long)M_*E_, (long)E_*E_, E_, (long)M_*E_, (long)M_*E_);
        }

        // --- guide attention: q from x2, kv from x1, overwrites x1 ---
        {
            const float* wi = attn_in_w  + (size_t)(l*3+2)*1536*E_;
            const float* bi = attn_in_b  + (size_t)(l*3+2)*1536;
            const float* wo = attn_out_w + (size_t)(l*3+2)*E_*E_;
            const float* bo = attn_out_b + (size_t)(l*3+2)*E_;
            splitTo(wi, h_Whi, h_Wlo, (size_t)1536*E_);   // rows 0..511 Q, 512..1535 KV
            gemmT(h_Ahi + (size_t)M_*256, h_Alo + (size_t)M_*256, 0,
                  bi, nullptr, nullptr, h_Qshi, h_Qslo,
                  M_, E_, E_, 0, 1, 0,0,0,0, (long)M_*E_);
            gemmT(h_Ahi, h_Alo, (long)E_*E_, bi + E_, nullptr, nullptr, h_KVhi, h_KVlo,
                  M_, 2*E_, E_, 0, 1, 0,0,0,0, (long)M_*2*E_);
            attn_kernel<<<256, 256, ATT_SMEM>>>(
                h_Qshi,       h_Qslo,       256, 0,
                h_KVhi,       h_KVlo,       512, 0,
                h_KVhi + 256, h_KVlo + 256, 512, 0,
                h_Ohi, h_Olo, 0);
            splitTo(wo, h_Whi, h_Wlo, (size_t)E_*E_);
            gemmT(h_Ohi, h_Olo, 0, bo, nullptr, x1p, nullptr, nullptr,
                  M_, E_, E_, 0, 1, 0,0,0,0,0);
        }

        // --- MLP, both streams in one M=12544 GEMM (shared weights) ---
        {
            const float* w1  = mlp_w1 + (size_t)l*4*E_*E_;
            const float* bb1 = mlp_b1 + (size_t)l*4*E_;
            const float* w2  = mlp_w2 + (size_t)l*E_*4*E_;
            const float* bb2 = mlp_b2 + (size_t)l*E_;
            ln_split_kernel<<<2*M_, 256>>>(xp, g1, b1, h_Ahi, h_Alo);
            splitTo(w1, h_Whi, h_Wlo, (size_t)4*E_*E_);
            gemmT(h_Ahi, h_Alo, 0, bb1, nullptr, nullptr, h_A2hi, h_A2lo,
                  2*M_, 4*E_, E_, 1, 1, 0,0,0,0, (long)2*M_*4*E_);
            splitTo(w2, h_Whi, h_Wlo, (size_t)E_*4*E_);
            gemmT(h_A2hi, h_A2lo, 0, bb2, xp, xp, nullptr, nullptr,
                  2*M_, E_, 4*E_, 0, 1, 0,0,0,0,0);
        }
    }

    // --- head (tiny; SIMT path) ---
    final_feat_kernel<<<64, 256>>>(fin_g, fin_b);
    gemmS(featp, cls_w1, cls_b1, nullptr, clshp, B_, 4*E_, 2*E_, 1);
    gemmS(clshp, cls_w2, cls_b2, nullptr, (float*)d_out, B_, NCLS_, 4*E_, 0);
}

// round 16
// speedup vs baseline: 1.3895x; 1.0045x over previous
#include <cuda_runtime.h>
#include <cuda_bf16.h>
#include <math.h>
#include <stdint.h>

#define B_   32
#define N_   196
#define E_   512
#define H_   8
#define HD_  64
#define L_   4
#define M_   (B_*N_)          // 6272 tokens
#define PD_  3840             // patch dim
#define NCLS_ 101
#define EPS_ 1e-5f

// ---------------- scratch (device globals; no cudaMalloc allowed) ------------
__device__ float g_x[2*M_*E_];
__device__ float g_feat[B_*2*E_];
__device__ float g_clsh[B_*4*E_];
// bf16 hi/lo split buffers (words = elems/2)
#define MAXA_W 12845056   // (12544*2048)/2
#define MAXW_W 11665408   // all weights pre-split: 23,330,816 elems / 2
__device__ uint32_t g_bfAhi[MAXA_W];
__device__ uint32_t g_bfAlo[MAXA_W];
__device__ uint32_t g_bfA2hi[MAXA_W];
__device__ uint32_t g_bfA2lo[MAXA_W];
__device__ uint32_t g_bfWhi[MAXW_W];
__device__ uint32_t g_bfWlo[MAXW_W];
__device__ uint32_t g_bfOhi[2*M_*256];     // attention output split
__device__ uint32_t g_bfOlo[2*M_*256];
__device__ uint32_t g_bfQshi[M_*256];      // guide Q split
__device__ uint32_t g_bfQslo[M_*256];
__device__ uint32_t g_bfKVhi[M_*512];      // guide KV split
__device__ uint32_t g_bfKVlo[M_*512];

// weight-buffer element offsets (all even)
#define WOFF_PW   0L                       // patch_w   512x3840
#define WOFF_TW   1966080L                 // text_w    512x768
#define WOFF_AIW  2359296L                 // attn_in_w (L,3,1536,512), block 786432
#define WOFF_AOW  11796480L                // attn_out_w (L,3,512,512), block 262144
#define WOFF_W1   14942208L                // mlp_w1 (L,2048,512), block 1048576
#define WOFF_W2   19136512L                // mlp_w2 (L,512,2048), block 1048576

// ---------------- PTX helpers (base compute_100-safe) ------------------------
__device__ __forceinline__ uint32_t smem_u32(const void* p) {
    uint32_t a;
    asm("{ .reg .u64 t; cvta.to.shared.u64 t, %1; cvt.u32.u64 %0, t; }" : "=r"(a) : "l"(p));
    return a;
}
__device__ __forceinline__ void ldm_x4(uint32_t addr, uint32_t* r) {
    asm volatile("ldmatrix.sync.aligned.m8n8.x4.shared.b16 {%0,%1,%2,%3}, [%4];"
        : "=r"(r[0]), "=r"(r[1]), "=r"(r[2]), "=r"(r[3]) : "r"(addr));
}
__device__ __forceinline__ void ldm_x4_t(uint32_t addr, uint32_t* r) {
    asm volatile("ldmatrix.sync.aligned.m8n8.x4.trans.shared.b16 {%0,%1,%2,%3}, [%4];"
        : "=r"(r[0]), "=r"(r[1]), "=r"(r[2]), "=r"(r[3]) : "r"(addr));
}
__device__ __forceinline__ void mma16816(float* c, const uint32_t* a, const uint32_t* b) {
    asm volatile("mma.sync.aligned.m16n8k16.row.col.f32.bf16.bf16.f32 "
        "{%0,%1,%2,%3}, {%4,%5,%6,%7}, {%8,%9}, {%0,%1,%2,%3};"
        : "+f"(c[0]), "+f"(c[1]), "+f"(c[2]), "+f"(c[3])
        : "r"(a[0]), "r"(a[1]), "r"(a[2]), "r"(a[3]), "r"(b[0]), "r"(b[1]));
}
__device__ __forceinline__ void cp16(uint32_t dst, const void* src) {
    asm volatile("cp.async.ca.shared.global [%0], [%1], 16;" :: "r"(dst), "l"(src));
}
#define CP_COMMIT() asm volatile("cp.async.commit_group;" ::: "memory")

__device__ __forceinline__ uint32_t pack_bf(float a, float b) {
    __nv_bfloat16 x = __float2bfloat16(a), y = __float2bfloat16(b);
    return ((uint32_t)__bfloat16_as_ushort(y) << 16) | __bfloat16_as_ushort(x);
}
__device__ __forceinline__ void split2(float a, float b, uint32_t& hi, uint32_t& lo) {
    __nv_bfloat16 ha = __float2bfloat16(a), hb = __float2bfloat16(b);
    hi = ((uint32_t)__bfloat16_as_ushort(hb) << 16) | __bfloat16_as_ushort(ha);
    lo = pack_bf(a - __bfloat162float(ha), b - __bfloat162float(hb));
}
__device__ __forceinline__ void cvt_hilo(float4 v, uint32_t& hi0, uint32_t& hi1,
                                         uint32_t& lo0, uint32_t& lo1) {
    split2(v.x, v.y, hi0, lo0);
    split2(v.z, v.w, hi1, lo1);
}

// ---------------- split: fp32 -> bf16 hi + lo --------------------------------
__global__ void split_kernel(const float4* __restrict__ in,
                             uint2* __restrict__ hi, uint2* __restrict__ lo, long n4)
{
    long i = (long)blockIdx.x * blockDim.x + threadIdx.x;
    if (i >= n4) return;
    float4 v = in[i];
    uint32_t h0, h1, l0, l1;
    cvt_hilo(v, h0, h1, l0, l1);
    hi[i] = make_uint2(h0, h1);
    lo[i] = make_uint2(l0, l1);
}

// ======= bf16 tensor-core GEMM: CTA 128x128, warp 64x32, 2-stage, occ 2 ======
#define ROWB 80
#define HOFF 10240
#define OFF_AL (1*HOFF)
#define OFF_BH (2*HOFF)
#define OFF_BL (3*HOFF)
#define BUFB   (4*HOFF)
#define GSMEM  (2*BUFB)            // 81920 -> 2 CTAs/SM

__global__ __launch_bounds__(256, 2)
void gemm_bf16_kernel(const __nv_bfloat16* __restrict__ Ahi,
                      const __nv_bfloat16* __restrict__ Alo,
                      const __nv_bfloat16* __restrict__ Bhi,
                      const __nv_bfloat16* __restrict__ Blo,
                      const float* __restrict__ bias,
                      const float* __restrict__ res,
                      float* __restrict__ C,
                      uint32_t* __restrict__ outHi,
                      uint32_t* __restrict__ outLo,
                      int M, int N, int K, int relu,
                      long sA, long sW, long sB, long sRes, long sC)
{
    int z = blockIdx.z;
    Ahi += (size_t)z * sA;  Alo += (size_t)z * sA;
    Bhi += (size_t)z * sW;  Blo += (size_t)z * sW;
    bias += (size_t)z * sB;
    if (res) res += (size_t)z * sRes;
    if (C)   C   += (size_t)z * sC;
    if (outHi) { outHi += (size_t)z * (sC >> 1); outLo += (size_t)z * (sC >> 1); }

    extern __shared__ char sm[];
    const uint32_t sbase = smem_u32(sm);
    const int tid = threadIdx.x, wid = tid >> 5, lane = tid & 31;
    const int m0 = blockIdx.y * 128, n0 = blockIdx.x * 128;
    const int wm = wid >> 2, wn = wid & 3;

    float acc[4][4][4];
#pragma unroll
    for (int i = 0; i < 4; i++)
#pragma unroll
        for (int j = 0; j < 4; j++)
#pragma unroll
            for (int r = 0; r < 4; r++) acc[i][j][r] = 0.f;

    const int c0row = tid >> 2, c0c = tid & 3;
    const int c1row = (tid + 256) >> 2, c1c = (tid + 256) & 3;

    auto issue = [&](int s, int buf) {
        uint32_t base = sbase + buf * BUFB;
        long kb = (long)s * 32;
        cp16(base + c0row * ROWB + c0c * 16,          Ahi + (size_t)(m0 + c0row) * K + kb + c0c * 8);
        cp16(base + OFF_AL + c0row * ROWB + c0c * 16, Alo + (size_t)(m0 + c0row) * K + kb + c0c * 8);
        cp16(base + c1row * ROWB + c1c * 16,          Ahi + (size_t)(m0 + c1row) * K + kb + c1c * 8);
        cp16(base + OFF_AL + c1row * ROWB + c1c * 16, Alo + (size_t)(m0 + c1row) * K + kb + c1c * 8);
        cp16(base + OFF_BH + c0row * ROWB + c0c * 16, Bhi + (size_t)(n0 + c0row) * K + kb + c0c * 8);
        cp16(base + OFF_BL + c0row * ROWB + c0c * 16, Blo + (size_t)(n0 + c0row) * K + kb + c0c * 8);
        cp16(base + OFF_BH + c1row * ROWB + c1c * 16, Bhi + (size_t)(n0 + c1row) * K + kb + c1c * 8);
        cp16(base + OFF_BL + c1row * ROWB + c1c * 16, Blo + (size_t)(n0 + c1row) * K + kb + c1c * 8);
    };

    const uint32_t aR = (uint32_t)(wm * 64 + (lane & 7) + ((lane >> 3) & 1) * 8);
    const uint32_t aC = (uint32_t)((lane >> 4) * 8);
    const uint32_t bR = (uint32_t)(wn * 32 + (lane & 7) + (lane >> 4) * 8);
    const uint32_t bC = (uint32_t)(((lane >> 3) & 1) * 8);

    auto compute = [&](int buf) {
        uint32_t bb = sbase + buf * BUFB;
#pragma unroll
        for (int kk = 0; kk < 32; kk += 16) {
            uint32_t ah[4][4], al[4][4], bh[2][4], bl[2][4];
#pragma unroll
            for (int mt = 0; mt < 4; mt++) {
                uint32_t off = (aR + mt * 16) * ROWB + (kk + aC) * 2;
                ldm_x4(bb + off, ah[mt]);
                ldm_x4(bb + OFF_AL + off, al[mt]);
            }
#pragma unroll
            for (int nt2 = 0; nt2 < 2; nt2++) {
                uint32_t off = (bR + nt2 * 16) * ROWB + (kk + bC) * 2;
                ldm_x4(bb + OFF_BH + off, bh[nt2]);
                ldm_x4(bb + OFF_BL + off, bl[nt2]);
            }
#pragma unroll
            for (int mt = 0; mt < 4; mt++)
#pragma unroll
                for (int nt = 0; nt < 4; nt++) {
                    const uint32_t* bhp = &bh[nt >> 1][(nt & 1) * 2];
                    const uint32_t* blp = &bl[nt >> 1][(nt & 1) * 2];
                    mma16816(acc[mt][nt], ah[mt], bhp);
                    mma16816(acc[mt][nt], ah[mt], blp);
                    mma16816(acc[mt][nt], al[mt], bhp);
                }
        }
    };

    const int nslab = K >> 5;
    issue(0, 0); CP_COMMIT();
    for (int s = 0; s < nslab; s++) {
        if (s + 1 < nslab) { issue(s + 1, (s + 1) & 1); CP_COMMIT(); }
        if (s + 1 < nslab) asm volatile("cp.async.wait_group 1;" ::: "memory");
        else               asm volatile("cp.async.wait_group 0;" ::: "memory");
        __syncthreads();
        compute(s & 1);
        __syncthreads();
    }

#pragma unroll
    for (int mt = 0; mt < 4; mt++)
#pragma unroll
        for (int nt = 0; nt < 4; nt++) {
            int m = m0 + wm * 64 + mt * 16 + (lane >> 2);
            int n = n0 + wn * 32 + nt * 8 + (lane & 3) * 2;
            float b0 = bias[n], b1 = bias[n + 1];
#pragma unroll
            for (int half = 0; half < 2; half++) {
                int mm = m + half * 8;
                float v0 = acc[mt][nt][half * 2]     + b0;
                float v1 = acc[mt][nt][half * 2 + 1] + b1;
                if (res) {
                    float2 r2 = *reinterpret_cast<const float2*>(res + (size_t)mm * N + n);
                    v0 += r2.x; v1 += r2.y;
                }
                if (relu) { v0 = fmaxf(v0, 0.f); v1 = fmaxf(v1, 0.f); }
                if (C)
                    *reinterpret_cast<float2*>(C + (size_t)mm * N + n) = make_float2(v0, v1);
                if (outHi) {
                    uint32_t hw, lw;
                    split2(v0, v1, hw, lw);
                    size_t wi = (size_t)mm * (N >> 1) + (n >> 1);
                    outHi[wi] = hw; outLo[wi] = lw;
                }
            }
        }
}

// ======== fused attention: S=QK^T (split mma), softmax, O=PV (split mma) =====
#define AK_ROW 144
#define A_KHI 0
#define A_KLO 34560
#define A_VHI 69120
#define A_VLO 103680
#define A_QHI 138240
#define A_QLO 147456
#define A_PROW 464
#define A_PHI 156672
#define A_PLO 186368
#define A_PMAX 216064
#define A_PSUM 217088
#define ATT_SMEM 218112

__global__ __launch_bounds__(256, 1)
void attn_kernel(const uint32_t* __restrict__ Qhi, const uint32_t* __restrict__ Qlo,
                 int qRowW, long qZW,
                 const uint32_t* __restrict__ Khi, const uint32_t* __restrict__ Klo,
                 int kRowW, long kZW,
                 const uint32_t* __restrict__ Vhi, const uint32_t* __restrict__ Vlo,
                 int vRowW, long vZW,
                 uint32_t* __restrict__ outHi, uint32_t* __restrict__ outLo, long outZW)
{
    extern __shared__ char sm[];
    const uint32_t sbase = smem_u32(sm);
    const int tid = threadIdx.x, wid = tid >> 5, lane = tid & 31;
    const int zz = blockIdx.x;
    const int z = zz >> 8, bh = zz & 255;
    const int b = bh >> 3, h = bh & 7;
    const int wm = wid >> 2, wn = wid & 3;
    float* pmax = (float*)(sm + A_PMAX);
    float* psum = (float*)(sm + A_PSUM);

    const uint4 z4 = make_uint4(0,0,0,0);
    for (int i = tid; i < 396; i += 256) {
        int r = 196 + i / 9, c = (i % 9) * 16;
        *(uint4*)(sm + A_KHI + r*AK_ROW + c) = z4;
        *(uint4*)(sm + A_KLO + r*AK_ROW + c) = z4;
        *(uint4*)(sm + A_VHI + r*AK_ROW + c) = z4;
        *(uint4*)(sm + A_VLO + r*AK_ROW + c) = z4;
    }
    for (int i = tid; i < 1568; i += 256) {
        int r = i >> 3, c = i & 7;
        size_t goff = (size_t)z * kZW + (size_t)(b*N_ + r) * kRowW + h*32 + c*4;
        cp16(sbase + A_KHI + r*AK_ROW + c*16, Khi + goff);
        cp16(sbase + A_KLO + r*AK_ROW + c*16, Klo + goff);
        size_t voff = (size_t)z * vZW + (size_t)(b*N_ + r) * vRowW + h*32 + c*4;
        cp16(sbase + A_VHI + r*AK_ROW + c*16, Vhi + voff);
        cp16(sbase + A_VLO + r*AK_ROW + c*16, Vlo + voff);
    }
    CP_COMMIT();
    asm volatile("cp.async.wait_group 0;" ::: "memory");
    __syncthreads();

    const uint32_t aRowLane = (uint32_t)((lane & 7) + ((lane >> 3) & 1) * 8);
    const uint32_t aColLane = (uint32_t)((lane >> 4) * 8);
    const uint32_t bRowLane = (uint32_t)((lane & 7) + (lane >> 4) * 8);
    const uint32_t bColLane = (uint32_t)(((lane >> 3) & 1) * 8);

    for (int qt = 0; qt < 4; qt++) {
        int q0 = qt * 64;
        __syncthreads();
        for (int i = tid; i < 512; i += 256) {
            int r = i >> 3, c = i & 7;
            int q = q0 + r;
            if (q < N_) {
                size_t goff = (size_t)z * qZW + (size_t)(b*N_ + q) * qRowW + h*32 + c*4;
                cp16(sbase + A_QHI + r*AK_ROW + c*16, Qhi + goff);
                cp16(sbase + A_QLO + r*AK_ROW + c*16, Qlo + goff);
            } else {
                *(uint4*)(sm + A_QHI + r*AK_ROW + c*16) = z4;
                *(uint4*)(sm + A_QLO + r*AK_ROW + c*16) = z4;
            }
        }
        CP_COMMIT();
        asm volatile("cp.async.wait_group 0;" ::: "memory");
        __syncthreads();

        float sacc[2][7][4];
#pragma unroll
        for (int i = 0; i < 2; i++)
#pragma unroll
            for (int j = 0; j < 7; j++)
#pragma unroll
                for (int r = 0; r < 4; r++) sacc[i][j][r] = 0.f;
#pragma unroll
        for (int ks = 0; ks < 4; ks++) {
            int koff = ks * 16;
            uint32_t ah[2][4], al[2][4], bh4[4][4], bl4[4][4];
#pragma unroll
            for (int mf = 0; mf < 2; mf++) {
                uint32_t off = (wm*32 + mf*16 + aRowLane) * AK_ROW + (koff + aColLane) * 2;
                ldm_x4(sbase + A_QHI + off, ah[mf]);
                ldm_x4(sbase + A_QLO + off, al[mf]);
            }
#pragma unroll
            for (int g = 0; g < 4; g++) {
                uint32_t off = (wn*56 + g*16 + bRowLane) * AK_ROW + (koff + bColLane) * 2;
                ldm_x4(sbase + A_KHI + off, bh4[g]);
                ldm_x4(sbase + A_KLO + off, bl4[g]);
            }
#pragma unroll
            for (int mf = 0; mf < 2; mf++)
#pragma unroll
                for (int nf = 0; nf < 7; nf++) {
                    const uint32_t* bhp = &bh4[nf >> 1][(nf & 1) * 2];
                    const uint32_t* blp = &bl4[nf >> 1][(nf & 1) * 2];
                    mma16816(sacc[mf][nf], ah[mf], bhp);
                    mma16816(sacc[mf][nf], ah[mf], blp);
                    mma16816(sacc[mf][nf], al[mf], bhp);
                }
        }

        float rmx[2][2] = {{-1e30f,-1e30f},{-1e30f,-1e30f}};
#pragma unroll
        for (int mf = 0; mf < 2; mf++)
#pragma unroll
            for (int nf = 0; nf < 7; nf++)
#pragma unroll
                for (int r = 0; r < 4; r++) {
                    int ncol = wn*56 + nf*8 + 2*(lane & 3) + (r & 1);
                    float v = sacc[mf][nf][r] * 0.125f;
                    if (ncol >= N_) v = -1e30f;
                    sacc[mf][nf][r] = v;
                    int rp = r >> 1;
                    rmx[mf][rp] = fmaxf(rmx[mf][rp], v);
                }
#pragma unroll
        for (int mf = 0; mf < 2; mf++)
#pragma unroll
            for (int rp = 0; rp < 2; rp++) {
                float v = rmx[mf][rp];
                v = fmaxf(v, __shfl_xor_sync(0xffffffffu, v, 1));
                v = fmaxf(v, __shfl_xor_sync(0xffffffffu, v, 2));
                rmx[mf][rp] = v;
                if ((lane & 3) == 0)
                    pmax[wn*64 + wm*32 + mf*16 + (lane >> 2) + rp*8] = v;
            }
        __syncthreads();
        float rsum[2][2] = {{0.f,0.f},{0.f,0.f}};
#pragma unroll
        for (int mf = 0; mf < 2; mf++)
#pragma unroll
            for (int rp = 0; rp < 2; rp++) {
                int row = wm*32 + mf*16 + (lane >> 2) + rp*8;
                float m0 = fmaxf(fmaxf(pmax[row], pmax[64+row]),
                                 fmaxf(pmax[128+row], pmax[192+row]));
                rmx[mf][rp] = m0;
            }
#pragma unroll
        for (int mf = 0; mf < 2; mf++)
#pragma unroll
            for (int nf = 0; nf < 7; nf++)
#pragma unroll
                for (int r = 0; r < 4; r++) {
                    float e = __expf(sacc[mf][nf][r] - rmx[mf][r >> 1]);
                    sacc[mf][nf][r] = e;
                    rsum[mf][r >> 1] += e;
                }
#pragma unroll
        for (int mf = 0; mf < 2; mf++)
#pragma unroll
            for (int rp = 0; rp < 2; rp++) {
                float v = rsum[mf][rp];
                v += __shfl_xor_sync(0xffffffffu, v, 1);
                v += __shfl_xor_sync(0xffffffffu, v, 2);
                if ((lane & 3) == 0)
                    psum[wn*64 + wm*32 + mf*16 + (lane >> 2) + rp*8] = v;
            }
#pragma unroll
        for (int mf = 0; mf < 2; mf++)
#pragma unroll
            for (int nf = 0; nf < 7; nf++) {
                int row = wm*32 + mf*16 + (lane >> 2);
                int col = wn*56 + nf*8 + 2*(lane & 3);
                uint32_t hw, lw;
                split2(sacc[mf][nf][0], sacc[mf][nf][1], hw, lw);
                *(uint32_t*)(sm + A_PHI + row*A_PROW + col*2) = hw;
                *(uint32_t*)(sm + A_PLO + row*A_PROW + col*2) = lw;
                split2(sacc[mf][nf][2], sacc[mf][nf][3], hw, lw);
                *(uint32_t*)(sm + A_PHI + (row+8)*A_PROW + col*2) = hw;
                *(uint32_t*)(sm + A_PLO + (row+8)*A_PROW + col*2) = lw;
            }
        __syncthreads();

        float oacc[2][2][4];
#pragma unroll
        for (int i = 0; i < 2; i++)
#pragma unroll
            for (int j = 0; j < 2; j++)
#pragma unroll
                for (int r = 0; r < 4; r++) oacc[i][j][r] = 0.f;
        const uint32_t vRowT = (uint32_t)(((lane >> 3) & 1) * 8 + (lane & 7));
        const uint32_t vColT = (uint32_t)(wn*16 + (lane >> 4) * 8);
#pragma unroll
        for (int ks = 0; ks < 14; ks++) {
            int koff = ks * 16;
            uint32_t pah[2][4], pal[2][4], vbh[4], vbl[4];
#pragma unroll
            for (int mf = 0; mf < 2; mf++) {
                uint32_t off = (wm*32 + mf*16 + aRowLane) * A_PROW + (koff + aColLane) * 2;
                ldm_x4(sbase + A_PHI + off, pah[mf]);
                ldm_x4(sbase + A_PLO + off, pal[mf]);
            }
            {
                uint32_t off = (koff + vRowT) * AK_ROW + vColT * 2;
                ldm_x4_t(sbase + A_VHI + off, vbh);
                ldm_x4_t(sbase + A_VLO + off, vbl);
            }
#pragma unroll
            for (int mf = 0; mf < 2; mf++)
#pragma unroll
                for (int ng = 0; ng < 2; ng++) {
                    mma16816(oacc[mf][ng], pah[mf], &vbh[ng*2]);
                    mma16816(oacc[mf][ng], pah[mf], &vbl[ng*2]);
                    mma16816(oacc[mf][ng], pal[mf], &vbh[ng*2]);
                }
        }
#pragma unroll
        for (int mf = 0; mf < 2; mf++)
#pragma unroll
            for (int ng = 0; ng < 2; ng++) {
                int col = wn*16 + ng*8 + 2*(lane & 3);
#pragma unroll
                for (int rp = 0; rp < 2; rp++) {
                    int row = wm*32 + mf*16 + (lane >> 2) + rp*8;
                    int q = q0 + row;
                    if (q < N_) {
                        float s0 = psum[row] + psum[64+row] + psum[128+row] + psum[192+row];
                        float inv = 1.f / s0;
                        float v0 = oacc[mf][ng][rp*2]     * inv;
                        float v1 = oacc[mf][ng][rp*2 + 1] * inv;
                        uint32_t hw, lw;
                        split2(v0, v1, hw, lw);
                        size_t wi = (size_t)z * outZW + (size_t)(b*N_ + q) * 256 + h*32 + (col >> 1);
                        outHi[wi] = hw; outLo[wi] = lw;
                    }
                }
            }
    }
}

// ------- fallback SIMT GEMM (head; any shape) --------------------------------
#define BM 128
#define BN 64
#define BK 16
__global__ __launch_bounds__(256, 2)
void gemm_kernel(const float* __restrict__ A,
                 const float* __restrict__ W,
                 const float* __restrict__ bias,
                 const float* __restrict__ res,
                 float* __restrict__ C,
                 int M, int N, int K, int relu)
{
    __shared__ float As[BK][BM+4];
    __shared__ float Ws[BK][BN+4];
    int tid = threadIdx.x;
    int tx = tid & 15, ty = tid >> 4;
    int m0 = blockIdx.y * BM, n0 = blockIdx.x * BN;
    float acc[8][4];
#pragma unroll
    for (int i = 0; i < 8; i++)
#pragma unroll
        for (int j = 0; j < 4; j++) acc[i][j] = 0.f;

    for (int k0 = 0; k0 < K; k0 += BK) {
#pragma unroll
        for (int t = 0; t < 2; t++) {
            int f = tid + t * 256;
            int r = f >> 2, kq = (f & 3) << 2;
            int m = m0 + r;
            float4 v = make_float4(0.f,0.f,0.f,0.f);
            if (m < M) v = *reinterpret_cast<const float4*>(A + (size_t)m*K + k0 + kq);
            As[kq][r]   = v.x; As[kq+1][r] = v.y;
            As[kq+2][r] = v.z; As[kq+3][r] = v.w;
        }
        {
            int r = tid >> 2, kq = (tid & 3) << 2;
            int n = n0 + r;
            float4 v = make_float4(0.f,0.f,0.f,0.f);
            if (n < N) v = *reinterpret_cast<const float4*>(W + (size_t)n*K + k0 + kq);
            Ws[kq][r]   = v.x; Ws[kq+1][r] = v.y;
            Ws[kq+2][r] = v.z; Ws[kq+3][r] = v.w;
        }
        __syncthreads();
#pragma unroll
        for (int kk = 0; kk < BK; kk++) {
            float a[8], b[4];
            *reinterpret_cast<float4*>(a)   = *reinterpret_cast<const float4*>(&As[kk][ty*8]);
            *reinterpret_cast<float4*>(a+4) = *reinterpret_cast<const float4*>(&As[kk][ty*8+4]);
            *reinterpret_cast<float4*>(b)   = *reinterpret_cast<const float4*>(&Ws[kk][tx*4]);
#pragma unroll
            for (int i = 0; i < 8; i++)
#pragma unroll
                for (int j = 0; j < 4; j++)
                    acc[i][j] += a[i]*b[j];
        }
        __syncthreads();
    }
#pragma unroll
    for (int i = 0; i < 8; i++) {
        int m = m0 + ty*8 + i;
        if (m >= M) continue;
#pragma unroll
        for (int j = 0; j < 4; j++) {
            int n = n0 + tx*4 + j;
            if (n >= N) continue;
            float v = acc[i][j] + bias[n];
            if (res) v += res[(size_t)m*N + n];
            if (relu) v = fmaxf(v, 0.f);
            C[(size_t)m*N + n] = v;
        }
    }
}

// ---------------- LayerNorm over 512 -> bf16 hi/lo split ---------------------
__global__ void ln_split_kernel(const float* __restrict__ x,
                                const float* __restrict__ g,
                                const float* __restrict__ b,
                                uint32_t* __restrict__ hi,
                                uint32_t* __restrict__ lo)
{
    int row = blockIdx.x;
    const float* xr = x + (size_t)row * E_;
    int tid = threadIdx.x;
    float2 v = *reinterpret_cast<const float2*>(xr + 2*tid);
    float s  = v.x + v.y;
    float ss = v.x*v.x + v.y*v.y;
#pragma unroll
    for (int o = 16; o > 0; o >>= 1) {
        s  += __shfl_xor_sync(0xffffffffu, s,  o);
        ss += __shfl_xor_sync(0xffffffffu, ss, o);
    }
    __shared__ float sh[16];
    int w = tid >> 5, lane = tid & 31;
    if (lane == 0) { sh[w] = s; sh[8+w] = ss; }
    __syncthreads();
    if (tid == 0) {
        float a = 0.f, c = 0.f;
        for (int i = 0; i < 8; i++) { a += sh[i]; c += sh[8+i]; }
        sh[0] = a; sh[8] = c;
    }
    __syncthreads();
    float mean = sh[0] * (1.f/E_);
    float var  = sh[8] * (1.f/E_) - mean*mean;
    float rs = rsqrtf(var + EPS_);
    float2 gg = *reinterpret_cast<const float2*>(g + 2*tid);
    float2 bb = *reinterpret_cast<const float2*>(b + 2*tid);
    float y0 = (v.x - mean) * rs * gg.x + bb.x;
    float y1 = (v.y - mean) * rs * gg.y + bb.y;
    uint32_t hw, lw;
    split2(y0, y1, hw, lw);
    size_t wi = (size_t)row * 256 + tid;
    hi[wi] = hw; lo[wi] = lw;
}

// ------- shifted-patch gather + LN(3840) -> bf16 hi/lo split -----------------
__global__ void patch_ln_kernel(const float* __restrict__ image,
                                const float* __restrict__ g,
                                const float* __restrict__ bb,
                                uint32_t* __restrict__ hi,
                                uint32_t* __restrict__ lo)
{
    __shared__ float buf[PD_];
    __shared__ float sh[16];
    int bn = blockIdx.x;
    int b  = bn / N_, n = bn % N_;
    int ph = n / 14, pw = n % 14;
    int tid = threadIdx.x;

    float s = 0.f, ss = 0.f;
    for (int d = tid; d < PD_; d += 256) {
        int c  = d % 15, t = d / 15;
        int p2 = t % 16, p1 = t / 16;
        int sh_idx = c / 3, ch = c % 3;
        int row = ph*16 + p1, col = pw*16 + p2;
        if      (sh_idx == 1) col -= 1;
        else if (sh_idx == 2) col += 1;
        else if (sh_idx == 3) row -= 1;
        else if (sh_idx == 4) row += 1;
        float v = 0.f;
        if (row >= 0 && row < 224 && col >= 0 && col < 224)
            v = image[(((size_t)b*3 + ch)*224 + row)*224 + col];
        buf[d] = v;
        s += v; ss += v*v;
    }
#pragma unroll
    for (int o = 16; o > 0; o >>= 1) {
        s  += __shfl_xor_sync(0xffffffffu, s,  o);
        ss += __shfl_xor_sync(0xffffffffu, ss, o);
    }
    int w = tid >> 5, lane = tid & 31;
    if (lane == 0) { sh[w] = s; sh[8+w] = ss; }
    __syncthreads();
    if (tid == 0) {
        float a = 0.f, c = 0.f;
        for (int i = 0; i < 8; i++) { a += sh[i]; c += sh[8+i]; }
        sh[0] = a; sh[8] = c;
    }
    __syncthreads();
    float mean = sh[0] * (1.f/PD_);
    float var  = sh[8] * (1.f/PD_) - mean*mean;
    float rs = rsqrtf(var + EPS_);
    uint32_t* hrow = hi + (size_t)bn * (PD_/2);
    uint32_t* lrow = lo + (size_t)bn * (PD_/2);
    for (int d = 2*tid; d < PD_; d += 512) {
        float y0 = (buf[d]   - mean) * rs * g[d]   + bb[d];
        float y1 = (buf[d+1] - mean) * rs * g[d+1] + bb[d+1];
        uint32_t hw, lw;
        split2(y0, y1, hw, lw);
        hrow[d >> 1] = hw; lrow[d >> 1] = lw;
    }
}

// ---------------- positional add (buggy batch-indexed sinusoid, per ref) -----
__global__ void posadd_kernel()
{
    int idx = blockIdx.x * 256 + threadIdx.x;
    if (idx >= 2*M_*E_) return;
    int e = idx & (E_-1);
    int stream_rem = idx % (M_*E_);
    int b = stream_rem / (N_*E_);
    float p = (float)(b + 1);
    int i = e & 255;
    float f = expf(-(float)i * (9.210340371976184f / 255.0f));
    float ang = p * f;
    float v = (e < 256) ? sinf(ang) : cosf(ang);
    g_x[idx] += v;
}

// ---------------- final LN of last token -> feat (B, 2E) ---------------------
__global__ void final_feat_kernel(const float* __restrict__ g,
                                  const float* __restrict__ b)
{
    int s = blockIdx.x >> 5;
    int bb = blockIdx.x & 31;
    const float* src = g_x + ((size_t)s*M_ + bb*N_ + (N_-1)) * E_;
    int tid = threadIdx.x;
    float v0 = src[tid], v1 = src[tid + 256];
    float ssum = v0 + v1, sq = v0*v0 + v1*v1;
#pragma unroll
    for (int o = 16; o > 0; o >>= 1) {
        ssum += __shfl_xor_sync(0xffffffffu, ssum, o);
        sq   += __shfl_xor_sync(0xffffffffu, sq,   o);
    }
    __shared__ float sh[16];
    int w = tid >> 5, lane = tid & 31;
    if (lane == 0) { sh[w] = ssum; sh[8+w] = sq; }
    __syncthreads();
    if (tid == 0) {
        float a = 0.f, c = 0.f;
        for (int i = 0; i < 8; i++) { a += sh[i]; c += sh[8+i]; }
        sh[0] = a; sh[8] = c;
    }
    __syncthreads();
    float mean = sh[0] * (1.f/E_);
    float var  = sh[8] * (1.f/E_) - mean*mean;
    float rs = rsqrtf(var + EPS_);
    float* dst = g_feat + (size_t)bb * (2*E_) + s*E_;
    dst[tid]       = (v0 - mean) * rs * g[tid]       + b[tid];
    dst[tid + 256] = (v1 - mean) * rs * g[tid + 256] + b[tid + 256];
}

// ---------------- host-side orchestration ------------------------------------
static uint32_t *h_Ahi, *h_Alo, *h_A2hi, *h_A2lo, *h_Whi, *h_Wlo;
static uint32_t *h_Ohi, *h_Olo, *h_Qshi, *h_Qslo, *h_KVhi, *h_KVlo;

static inline void splitTo(const float* src, uint32_t* hi, uint32_t* lo, size_t n)
{
    long n4 = (long)(n >> 2);
    split_kernel<<<(unsigned)((n4 + 255) / 256), 256>>>(
        (const float4*)src, (uint2*)hi, (uint2*)lo, n4);
}
static inline void gemmT(const uint32_t* aHi, const uint32_t* aLo, long wElemOff,
                         const float* bias, const float* res, float* C,
                         uint32_t* oHi, uint32_t* oLo,
                         int M, int N, int K, int relu, int nz,
                         long sA, long sW, long sB, long sRes, long sC)
{
    dim3 grid(N / 128, M / 128, nz);
    gemm_bf16_kernel<<<grid, 256, GSMEM>>>(
        (const __nv_bfloat16*)aHi, (const __nv_bfloat16*)aLo,
        (const __nv_bfloat16*)h_Whi + wElemOff, (const __nv_bfloat16*)h_Wlo + wElemOff,
        bias, res, C, oHi, oLo, M, N, K, relu, sA, sW, sB, sRes, sC);
}
static inline void gemmS(const float* A, const float* W, const float* bias,
                         const float* res, float* C, int M, int N, int K, int relu)
{
    dim3 grid((N + BN - 1)/BN, (M + BM - 1)/BM);
    gemm_kernel<<<grid, 256>>>(A, W, bias, res, C, M, N, K, relu);
}

extern "C" void kernel_launch(void* const* d_in, const int* in_sizes, int n_in,
                              void* d_out, int out_size)
{
    const float* image      = (const float*)d_in[0];
    const float* text_hidden= (const float*)d_in[1];
    const float* patch_ln_g = (const float*)d_in[2];
    const float* patch_ln_b = (const float*)d_in[3];
    const float* patch_w    = (const float*)d_in[4];
    const float* patch_b    = (const float*)d_in[5];
    const float* text_w     = (const float*)d_in[6];
    const float* text_b     = (const float*)d_in[7];
    const float* attn_in_w  = (const float*)d_in[8];
    const float* attn_in_b  = (const float*)d_in[9];
    const float* attn_out_w = (const float*)d_in[10];
    const float* attn_out_b = (const float*)d_in[11];
    const float* mlp_w1     = (const float*)d_in[12];
    const float* mlp_b1     = (const float*)d_in[13];
    const float* mlp_w2     = (const float*)d_in[14];
    const float* mlp_b2     = (const float*)d_in[15];
    const float* ln_gamma   = (const float*)d_in[16];
    const float* ln_beta    = (const float*)d_in[17];
    const float* fin_g      = (const float*)d_in[18];
    const float* fin_b      = (const float*)d_in[19];
    const float* cls_w1     = (const float*)d_in[20];
    const float* cls_b1     = (const float*)d_in[21];
    const float* cls_w2     = (const float*)d_in[22];
    const float* cls_b2     = (const float*)d_in[23];

    cudaFuncSetAttribute(gemm_bf16_kernel,
                         cudaFuncAttributeMaxDynamicSharedMemorySize, GSMEM);
    cudaFuncSetAttribute(attn_kernel,
                         cudaFuncAttributeMaxDynamicSharedMemorySize, ATT_SMEM);

    float *xp,*featp,*clshp;
    cudaGetSymbolAddress((void**)&xp,    g_x);
    cudaGetSymbolAddress((void**)&featp, g_feat);
    cudaGetSymbolAddress((void**)&clshp, g_clsh);
    cudaGetSymbolAddress((void**)&h_Ahi,  g_bfAhi);
    cudaGetSymbolAddress((void**)&h_Alo,  g_bfAlo);
    cudaGetSymbolAddress((void**)&h_A2hi, g_bfA2hi);
    cudaGetSymbolAddress((void**)&h_A2lo, g_bfA2lo);
    cudaGetSymbolAddress((void**)&h_Whi,  g_bfWhi);
    cudaGetSymbolAddress((void**)&h_Wlo,  g_bfWlo);
    cudaGetSymbolAddress((void**)&h_Ohi,  g_bfOhi);
    cudaGetSymbolAddress((void**)&h_Olo,  g_bfOlo);
    cudaGetSymbolAddress((void**)&h_Qshi, g_bfQshi);
    cudaGetSymbolAddress((void**)&h_Qslo, g_bfQslo);
    cudaGetSymbolAddress((void**)&h_KVhi, g_bfKVhi);
    cudaGetSymbolAddress((void**)&h_KVlo, g_bfKVlo);

    float* x1p = xp;

    // --- pre-split ALL weights once (6 launches, streaming) ---
    splitTo(patch_w,    h_Whi + WOFF_PW/2,  h_Wlo + WOFF_PW/2,  (size_t)E_*PD_);
    splitTo(text_w,     h_Whi + WOFF_TW/2,  h_Wlo + WOFF_TW/2,  (size_t)E_*768);
    splitTo(attn_in_w,  h_Whi + WOFF_AIW/2, h_Wlo + WOFF_AIW/2, (size_t)L_*3*1536*E_);
    splitTo(attn_out_w, h_Whi + WOFF_AOW/2, h_Wlo + WOFF_AOW/2, (size_t)L_*3*E_*E_);
    splitTo(mlp_w1,     h_Whi + WOFF_W1/2,  h_Wlo + WOFF_W1/2,  (size_t)L_*4*E_*E_);
    splitTo(mlp_w2,     h_Whi + WOFF_W2/2,  h_Wlo + WOFF_W2/2,  (size_t)L_*E_*4*E_);

    // --- embedding ---
    patch_ln_kernel<<<M_, 256>>>(image, patch_ln_g, patch_ln_b, h_Ahi, h_Alo);
    gemmT(h_Ahi, h_Alo, WOFF_PW, patch_b, nullptr, x1p, nullptr, nullptr,
          M_, E_, PD_, 0, 1, 0,0,0,0,0);
    splitTo(text_hidden, h_Ahi, h_Alo, (size_t)M_*768);
    gemmT(h_Ahi, h_Alo, WOFF_TW, text_b, nullptr, xp + (size_t)M_*E_, nullptr, nullptr,
          M_, E_, 768, 0, 1, 0,0,0,0,0);
    posadd_kernel<<<(2*M_*E_ + 255)/256, 256>>>();

    for (int l = 0; l < L_; l++) {
        const float* g0 = ln_gamma + (size_t)(l*2+0)*E_;
        const float* b0 = ln_beta  + (size_t)(l*2+0)*E_;
        const float* g1 = ln_gamma + (size_t)(l*2+1)*E_;
        const float* b1 = ln_beta  + (size_t)(l*2+1)*E_;
        long aiw = WOFF_AIW + (long)(l*3) * 1536 * E_;
        long aow = WOFF_AOW + (long)(l*3) * E_ * E_;
        long giw = WOFF_AIW + (long)(l*3+2) * 1536 * E_;
        long gow = WOFF_AOW + (long)(l*3+2) * E_ * E_;
        long w1o = WOFF_W1 + (long)l * 4 * E_ * E_;
        long w2o = WOFF_W2 + (long)l * E_ * 4 * E_;

        // --- self-attention, both streams batched (z = stream) ---
        {
            const float* bi = attn_in_b  + (size_t)(l*3)*1536;
            const float* bo = attn_out_b + (size_t)(l*3)*E_;
            ln_split_kernel<<<2*M_, 256>>>(xp, g0, b0, h_Ahi, h_Alo);
            gemmT(h_Ahi, h_Alo, aiw, bi, nullptr, nullptr, h_A2hi, h_A2lo,
                  M_, 1536, E_, 0, 2,
                  (long)M_*E_, (long)1536*E_, 1536, 0, (long)M_*1536);
            attn_kernel<<<512, 256, ATT_SMEM>>>(
                h_A2hi,       h_A2lo,       768, (long)M_*768,
                h_A2hi + 256, h_A2lo + 256, 768, (long)M_*768,
                h_A2hi + 512, h_A2lo + 512, 768, (long)M_*768,
                h_Ohi, h_Olo, (long)M_*256);
            // writes fp32 x and its bf16 split (split consumed by guide attention)
            gemmT(h_Ohi, h_Olo, aow, bo, xp, xp, h_Ahi, h_Alo,
                  M_, E_, E_, 0, 2,
                  (long)M_*E_, (long)E_*E_, E_, (long)M_*E_, (long)M_*E_);
        }

        // --- guide attention: q from x2, kv from x1, overwrites x1 ---
        {
            const float* bi = attn_in_b  + (size_t)(l*3+2)*1536;
            const float* bo = attn_out_b + (size_t)(l*3+2)*E_;
            gemmT(h_Ahi + (size_t)M_*256, h_Alo + (size_t)M_*256, giw,
                  bi, nullptr, nullptr, h_Qshi, h_Qslo,
                  M_, E_, E_, 0, 1, 0,0,0,0, (long)M_*E_);
            gemmT(h_Ahi, h_Alo, giw + (long)E_*E_, bi + E_, nullptr, nullptr, h_KVhi, h_KVlo,
                  M_, 2*E_, E_, 0, 1, 0,0,0,0, (long)M_*2*E_);
            attn_kernel<<<256, 256, ATT_SMEM>>>(
                h_Qshi,       h_Qslo,       256, 0,
                h_KVhi,       h_KVlo,       512, 0,
                h_KVhi + 256, h_KVlo + 256, 512, 0,
                h_Ohi, h_Olo, 0);
            gemmT(h_Ohi, h_Olo, gow, bo, nullptr, x1p, nullptr, nullptr,
                  M_, E_, E_, 0, 1, 0,0,0,0,0);
        }

        // --- MLP, both streams in one M=12544 GEMM (shared weights) ---
        {
            const float* bb1 = mlp_b1 + (size_t)l*4*E_;
            const float* bb2 = mlp_b2 + (size_t)l*E_;
            ln_split_kernel<<<2*M_, 256>>>(xp, g1, b1, h_Ahi, h_Alo);
            gemmT(h_Ahi, h_Alo, w1o, bb1, nullptr, nullptr, h_A2hi, h_A2lo,
                  2*M_, 4*E_, E_, 1, 1, 0,0,0,0, (long)2*M_*4*E_);
            gemmT(h_A2hi, h_A2lo, w2o, bb2, xp, xp, nullptr, nullptr,
                  2*M_, E_, 4*E_, 0, 1, 0,0,0,0,0);
        }
    }

    // --- head (tiny; SIMT path) ---
    final_feat_kernel<<<64, 256>>>(fin_g, fin_b);
    gemmS(featp, cls_w1, cls_b1, nullptr, clshp, B_, 4*E_, 2*E_, 1);
    gemmS(clshp, cls_w2, cls_b2, nullptr, (float*)d_out, B_, NCLS_, 4*E_, 0);
}